// round 4
// baseline (speedup 1.0000x reference)
#include <cuda_runtime.h>
#include <cstdint>

// ---------------------------------------------------------------------------
// Problem constants (fixed shapes)
// ---------------------------------------------------------------------------
#define LQ   2048      // sequence length
#define DIM  2048
#define NH   16        // heads
#define HD   128       // head dim
#define QKV_N (3*DIM)  // 6144

// Scratch (allocation-free rule: __device__ globals)
__device__ float g_qkv[(size_t)LQ * QKV_N];                 // [L, 6144]  q|k|v interleaved per row
__device__ float g_S  [(size_t)NH * LQ * LQ];               // [H, L, L]  scores / probs
__device__ float g_att[(size_t)LQ * DIM];                   // [L, H*HD]  attention output

// ---------------------------------------------------------------------------
// Generic tiled SGEMM:  C[m,n] = sum_k A[m,k] * B(k,n)   (+ bias[n])
//   TRANS_B = true : B is [N,K] row-major (B(k,n) = B[n*ldb + k])   => A @ B^T
//   TRANS_B = false: B is [K,N] row-major (B(k,n) = B[k*ldb + n])   => A @ B
// Batched over blockIdx.z with element strides sA/sB/sC.
// Requires M%BM==0, N%BN==0, K%BK==0, all pointers/ld 16B-friendly.
// ---------------------------------------------------------------------------
template<int BM, int BN, int BK, bool TRANS_B, bool BIAS>
__global__ __launch_bounds__(256, 2)
void gemm_kernel(const float* __restrict__ Ag, const float* __restrict__ Bg,
                 float* __restrict__ Cg, const float* __restrict__ bias,
                 int M, int N, int K, int lda, int ldb, int ldc,
                 long sA, long sB, long sC)
{
    constexpr int TM = 8, TN = 8;
    constexpr int THREADS = (BM / TM) * (BN / TN);   // 256

    __shared__ float As[BK][BM];
    __shared__ float Bs[BK][BN];

    const int tid = threadIdx.x;
    const int tx  = tid % (BN / TN);   // 0..15 (n dir)
    const int ty  = tid / (BN / TN);   // 0..15 (m dir)
    const int m0  = blockIdx.y * BM;
    const int n0  = blockIdx.x * BN;

    const float* A = Ag + (size_t)blockIdx.z * sA;
    const float* B = Bg + (size_t)blockIdx.z * sB;
    float*       C = Cg + (size_t)blockIdx.z * sC;

    float acc[TM][TN];
#pragma unroll
    for (int i = 0; i < TM; i++)
#pragma unroll
        for (int j = 0; j < TN; j++) acc[i][j] = 0.f;

    for (int k0 = 0; k0 < K; k0 += BK) {
        // ---- stage A tile [BM x BK] transposed into As[k][m] ----
#pragma unroll
        for (int i = tid; i < BM * BK / 4; i += THREADS) {
            const int row = i >> 2;            // m within tile
            const int kq  = (i & 3) << 2;      // k within tile (x4)
            const float4 v = *(const float4*)(A + (size_t)(m0 + row) * lda + k0 + kq);
            As[kq + 0][row] = v.x;
            As[kq + 1][row] = v.y;
            As[kq + 2][row] = v.z;
            As[kq + 3][row] = v.w;
        }
        // ---- stage B tile into Bs[k][n] ----
        if (TRANS_B) {
#pragma unroll
            for (int i = tid; i < BN * BK / 4; i += THREADS) {
                const int row = i >> 2;        // n within tile
                const int kq  = (i & 3) << 2;
                const float4 v = *(const float4*)(B + (size_t)(n0 + row) * ldb + k0 + kq);
                Bs[kq + 0][row] = v.x;
                Bs[kq + 1][row] = v.y;
                Bs[kq + 2][row] = v.z;
                Bs[kq + 3][row] = v.w;
            }
        } else {
#pragma unroll
            for (int i = tid; i < BK * BN / 4; i += THREADS) {
                const int kk = i / (BN / 4);
                const int nq = (i % (BN / 4)) << 2;
                const float4 v = *(const float4*)(B + (size_t)(k0 + kk) * ldb + n0 + nq);
                *(float4*)&Bs[kk][nq] = v;
            }
        }
        __syncthreads();

        // ---- compute ----
#pragma unroll
        for (int kk = 0; kk < BK; kk++) {
            float a[TM], b[TN];
#pragma unroll
            for (int i = 0; i < TM; i++) a[i] = As[kk][ty * TM + i];
#pragma unroll
            for (int j = 0; j < TN; j++) b[j] = Bs[kk][tx * TN + j];
#pragma unroll
            for (int i = 0; i < TM; i++)
#pragma unroll
                for (int j = 0; j < TN; j++) acc[i][j] = fmaf(a[i], b[j], acc[i][j]);
        }
        __syncthreads();
    }

    // ---- epilogue ----
#pragma unroll
    for (int i = 0; i < TM; i++) {
        const int m = m0 + ty * TM + i;
#pragma unroll
        for (int j = 0; j < TN; j += 4) {
            const int n = n0 + tx * TN + j;
            float4 v;
            v.x = acc[i][j + 0];
            v.y = acc[i][j + 1];
            v.z = acc[i][j + 2];
            v.w = acc[i][j + 3];
            if (BIAS) {
                v.x += bias[n + 0];
                v.y += bias[n + 1];
                v.z += bias[n + 2];
                v.w += bias[n + 3];
            }
            *(float4*)(C + (size_t)m * ldc + n) = v;
        }
    }
}

// ---------------------------------------------------------------------------
// Per-(qk, head, l) RMSNorm (eps=1e-6, over HD) + RoPE, in place on g_qkv.
// grid = 2*NH*L blocks, 128 threads (one per head-dim element).
// RoPE: new[2j+s] = pe[l,j,s,0]*t[2j] + pe[l,j,s,1]*t[2j+1]
// ---------------------------------------------------------------------------
__global__ void norm_rope_kernel(const float* __restrict__ pe,
                                 const float* __restrict__ q_scale,
                                 const float* __restrict__ k_scale)
{
    const int idx = blockIdx.x;
    const int l   = idx & (LQ - 1);
    const int h   = (idx >> 11) & (NH - 1);
    const int qk  = idx >> 15;                  // 0 = q, 1 = k
    const int d   = threadIdx.x;                // 0..127
    const int lane = d & 31, warp = d >> 5;

    float* row = g_qkv + (size_t)l * QKV_N + qk * DIM + h * HD;
    const float t = row[d];

    // sum of squares over 128 threads
    float ss = t * t;
#pragma unroll
    for (int o = 16; o > 0; o >>= 1) ss += __shfl_xor_sync(0xFFFFFFFFu, ss, o);
    __shared__ float red[4];
    if (lane == 0) red[warp] = ss;
    __syncthreads();
    const float tot = red[0] + red[1] + red[2] + red[3];
    const float rrms = rsqrtf(tot * (1.0f / HD) + 1e-6f);

    const float* scale = qk ? k_scale : q_scale;
    const float tn = t * rrms * scale[d];

    // RoPE (pair partner is lane^1 — same warp)
    const float other = __shfl_xor_sync(0xFFFFFFFFu, tn, 1);
    const int j = d >> 1, s = d & 1;
    const float* pp = pe + ((size_t)l * (HD / 2) + j) * 4 + s * 2;
    const float te = (s == 0) ? tn : other;     // t[2j]
    const float to = (s == 0) ? other : tn;     // t[2j+1]
    row[d] = pp[0] * te + pp[1] * to;
}

// ---------------------------------------------------------------------------
// Row softmax over g_S: 16*2048 rows of 2048, scale 1/sqrt(HD) before exp.
// 256 threads/row, 8 elems/thread.
// ---------------------------------------------------------------------------
__global__ void softmax_kernel()
{
    constexpr float SCALE = 0.08838834764831845f;  // 1/sqrt(128)
    float* p = g_S + (size_t)blockIdx.x * LQ;
    const int tid = threadIdx.x;
    const int lane = tid & 31, warp = tid >> 5;
    __shared__ float red[8];

    float v[8];
    float mx = -3.4e38f;
#pragma unroll
    for (int i = 0; i < 8; i++) {
        v[i] = p[tid + i * 256];
        mx = fmaxf(mx, v[i]);
    }
#pragma unroll
    for (int o = 16; o > 0; o >>= 1) mx = fmaxf(mx, __shfl_xor_sync(0xFFFFFFFFu, mx, o));
    if (lane == 0) red[warp] = mx;
    __syncthreads();
    float m = red[0];
#pragma unroll
    for (int i = 1; i < 8; i++) m = fmaxf(m, red[i]);
    __syncthreads();

    float sum = 0.f;
#pragma unroll
    for (int i = 0; i < 8; i++) {
        v[i] = __expf((v[i] - m) * SCALE);
        sum += v[i];
    }
#pragma unroll
    for (int o = 16; o > 0; o >>= 1) sum += __shfl_xor_sync(0xFFFFFFFFu, sum, o);
    if (lane == 0) red[warp] = sum;
    __syncthreads();
    float tot = red[0];
#pragma unroll
    for (int i = 1; i < 8; i++) tot += red[i];
    const float inv = 1.0f / tot;

#pragma unroll
    for (int i = 0; i < 8; i++) p[tid + i * 256] = v[i] * inv;
}

// ---------------------------------------------------------------------------
// Launch
// Inputs: x, pe, qkv_w, q_scale, k_scale, proj_w, proj_b   (all f32)
// Output: [1, 2048, 2048] f32
// ---------------------------------------------------------------------------
extern "C" void kernel_launch(void* const* d_in, const int* in_sizes, int n_in,
                              void* d_out, int out_size)
{
    const float* x       = (const float*)d_in[0];
    const float* pe      = (const float*)d_in[1];
    const float* qkv_w   = (const float*)d_in[2];
    const float* q_scale = (const float*)d_in[3];
    const float* k_scale = (const float*)d_in[4];
    const float* proj_w  = (const float*)d_in[5];
    const float* proj_b  = (const float*)d_in[6];
    float* out = (float*)d_out;

    float *qkv, *S, *att;
    cudaGetSymbolAddress((void**)&qkv, g_qkv);
    cudaGetSymbolAddress((void**)&S,   g_S);
    cudaGetSymbolAddress((void**)&att, g_att);

    // 1) qkv = x @ qkv_w^T       [2048,6144]
    {
        dim3 grid(QKV_N / 128, LQ / 128, 1);
        gemm_kernel<128,128,16,true,false><<<grid, 256>>>(
            x, qkv_w, qkv, nullptr,
            LQ, QKV_N, DIM, DIM, DIM, QKV_N, 0, 0, 0);
    }

    // 2) per-head RMSNorm + RoPE on q and k (in place)
    norm_rope_kernel<<<2 * NH * LQ, 128>>>(pe, q_scale, k_scale);

    // 3) scores per head: S_h = Q_h @ K_h^T  (scale folded into softmax)
    {
        dim3 grid(LQ / 128, LQ / 128, NH);
        gemm_kernel<128,128,16,true,false><<<grid, 256>>>(
            qkv /*Q base*/, qkv + DIM /*K base*/, S, nullptr,
            LQ, LQ, HD, QKV_N, QKV_N, LQ,
            /*sA=*/HD, /*sB=*/HD, /*sC=*/(long)LQ * LQ);
    }

    // 4) softmax rows
    softmax_kernel<<<NH * LQ, 256>>>();

    // 5) attn_out_h = P_h @ V_h   (B non-transposed: V[k,n] at qkv[k*6144 + 2*DIM + h*128 + n])
    {
        dim3 grid(HD / 128, LQ / 128, NH);
        gemm_kernel<128,128,16,false,false><<<grid, 256>>>(
            S, qkv + 2 * DIM, att, nullptr,
            LQ, HD, LQ, LQ, QKV_N, DIM,
            /*sA=*/(long)LQ * LQ, /*sB=*/HD, /*sC=*/HD);
    }

    // 6) out = att @ proj_w^T + proj_b
    {
        dim3 grid(DIM / 128, LQ / 128, 1);
        gemm_kernel<128,128,16,true,true><<<grid, 256>>>(
            att, proj_w, out, proj_b,
            LQ, DIM, DIM, DIM, DIM, DIM, 0, 0, 0);
    }
}

// round 7
// speedup vs baseline: 1.0552x; 1.0552x over previous
#include <cuda_runtime.h>
#include <cstdint>

// ---------------------------------------------------------------------------
// Problem constants (fixed shapes)
// ---------------------------------------------------------------------------
#define LQ   2048      // sequence length
#define DIM  2048
#define NH   16        // heads
#define HD   128       // head dim
#define QKV_N (3*DIM)  // 6144

// Scratch (allocation-free rule: __device__ globals)
__device__ float g_qkv[(size_t)LQ * QKV_N];   // [L, 6144]  q|k|v per row
__device__ float g_S  [(size_t)NH * LQ * LQ]; // [H, L, L]  scores / probs
__device__ float g_att[(size_t)LQ * DIM];     // [L, H*HD]

// ---------------------------------------------------------------------------
// tf32 helpers
// ---------------------------------------------------------------------------
__device__ __forceinline__ uint32_t f2tf32(float f) {
    uint32_t u;
    asm("cvt.rna.tf32.f32 %0, %1;" : "=r"(u) : "f"(f));
    return u;
}

// split-precision decomposition: f = hi + lo (each exactly representable in tf32)
__device__ __forceinline__ void split_tf32(float f, uint32_t& hi, uint32_t& lo) {
    hi = f2tf32(f);
    lo = f2tf32(f - __uint_as_float(hi));
}

__device__ __forceinline__ void mma_tf32(float c[4],
                                         uint32_t a0, uint32_t a1, uint32_t a2, uint32_t a3,
                                         uint32_t b0, uint32_t b1) {
    asm volatile(
        "mma.sync.aligned.m16n8k8.row.col.f32.tf32.tf32.f32 "
        "{%0,%1,%2,%3}, {%4,%5,%6,%7}, {%8,%9}, {%0,%1,%2,%3};"
        : "+f"(c[0]), "+f"(c[1]), "+f"(c[2]), "+f"(c[3])
        : "r"(a0), "r"(a1), "r"(a2), "r"(a3), "r"(b0), "r"(b1));
}

// ---------------------------------------------------------------------------
// tf32x3 tensor-core GEMM (fp32-accurate): C = A @ B(^T) (+bias)
//   TRANS_B=true : B row-major [N,K]  => A @ B^T
//   TRANS_B=false: B row-major [K,N]  => A @ B
// CTA tile 128x64x16, 8 warps (2x4), warp tile 64x16 (4x2 m16n8 frags).
// Each product computed as hi*hi + hi*lo + lo*hi  (3 MMAs).
// Batched over blockIdx.z (element strides sA/sB/sC).
// Requires M%128==0, N%64==0, K%16==0, 16B-aligned rows.
// ---------------------------------------------------------------------------
template<bool TRANS_B, bool BIAS>
__global__ __launch_bounds__(256, 2)
void mma_gemm(const float* __restrict__ Ag, const float* __restrict__ Bg,
              float* __restrict__ Cg, const float* __restrict__ bias,
              int M, int N, int K, int lda, int ldb, int ldc,
              long sA, long sB, long sC)
{
    constexpr int BM = 128, BN = 64, BK = 16, BKP = BK + 4;

    __shared__ uint32_t As_hi[BM][BKP], As_lo[BM][BKP];
    __shared__ uint32_t Bs_hi[BN][BKP], Bs_lo[BN][BKP];

    const int tid  = threadIdx.x;
    const int warp = tid >> 5;
    const int lane = tid & 31;
    const int wm   = (warp >> 2) * 64;   // warp m-origin (2 warp-rows)
    const int wn   = (warp & 3) * 16;    // warp n-origin (4 warp-cols)
    const int m0   = blockIdx.y * BM;
    const int n0   = blockIdx.x * BN;

    const float* A = Ag + (size_t)blockIdx.z * sA;
    const float* B = Bg + (size_t)blockIdx.z * sB;
    float*       C = Cg + (size_t)blockIdx.z * sC;

    float acc[4][2][4];
#pragma unroll
    for (int i = 0; i < 4; i++)
#pragma unroll
        for (int j = 0; j < 2; j++)
#pragma unroll
            for (int r = 0; r < 4; r++) acc[i][j][r] = 0.f;

    const int ar = lane >> 2, ac = lane & 3;   // A-frag row/col
    const int br = lane & 3,  bc = lane >> 2;  // B-frag k/n

    for (int k0 = 0; k0 < K; k0 += BK) {
        // ---- stage A tile [BM x BK] -> As_{hi,lo}[m][k] ----
#pragma unroll
        for (int i = tid; i < BM * BK / 4; i += 256) {
            const int m  = i >> 2;
            const int kq = (i & 3) << 2;
            const float4 v = *(const float4*)(A + (size_t)(m0 + m) * lda + k0 + kq);
            uint32_t h0, l0, h1, l1, h2, l2, h3, l3;
            split_tf32(v.x, h0, l0); split_tf32(v.y, h1, l1);
            split_tf32(v.z, h2, l2); split_tf32(v.w, h3, l3);
            uint4 th = {h0, h1, h2, h3};
            uint4 tl = {l0, l1, l2, l3};
            *(uint4*)&As_hi[m][kq] = th;
            *(uint4*)&As_lo[m][kq] = tl;
        }
        // ---- stage B tile -> Bs_{hi,lo}[n][k] ----
        if (TRANS_B) {
#pragma unroll
            for (int i = tid; i < BN * BK / 4; i += 256) {
                const int n  = i >> 2;
                const int kq = (i & 3) << 2;
                const float4 v = *(const float4*)(B + (size_t)(n0 + n) * ldb + k0 + kq);
                uint32_t h0, l0, h1, l1, h2, l2, h3, l3;
                split_tf32(v.x, h0, l0); split_tf32(v.y, h1, l1);
                split_tf32(v.z, h2, l2); split_tf32(v.w, h3, l3);
                uint4 th = {h0, h1, h2, h3};
                uint4 tl = {l0, l1, l2, l3};
                *(uint4*)&Bs_hi[n][kq] = th;
                *(uint4*)&Bs_lo[n][kq] = tl;
            }
        } else {
#pragma unroll
            for (int i = tid; i < BK * BN / 4; i += 256) {
                const int kk = i >> 4;           // 0..15
                const int nq = (i & 15) << 2;    // 0..60
                const float4 v = *(const float4*)(B + (size_t)(k0 + kk) * ldb + n0 + nq);
                uint32_t h, l;
                split_tf32(v.x, h, l); Bs_hi[nq + 0][kk] = h; Bs_lo[nq + 0][kk] = l;
                split_tf32(v.y, h, l); Bs_hi[nq + 1][kk] = h; Bs_lo[nq + 1][kk] = l;
                split_tf32(v.z, h, l); Bs_hi[nq + 2][kk] = h; Bs_lo[nq + 2][kk] = l;
                split_tf32(v.w, h, l); Bs_hi[nq + 3][kk] = h; Bs_lo[nq + 3][kk] = l;
            }
        }
        __syncthreads();

        // ---- compute: 2 k-steps of 8, tf32x3 per step ----
#pragma unroll
        for (int ks = 0; ks < BK; ks += 8) {
            uint32_t afh[4][4], afl[4][4];
#pragma unroll
            for (int mt = 0; mt < 4; mt++) {
                const int mb = wm + mt * 16;
                afh[mt][0] = As_hi[mb + ar    ][ks + ac    ];
                afh[mt][1] = As_hi[mb + ar + 8][ks + ac    ];
                afh[mt][2] = As_hi[mb + ar    ][ks + ac + 4];
                afh[mt][3] = As_hi[mb + ar + 8][ks + ac + 4];
                afl[mt][0] = As_lo[mb + ar    ][ks + ac    ];
                afl[mt][1] = As_lo[mb + ar + 8][ks + ac    ];
                afl[mt][2] = As_lo[mb + ar    ][ks + ac + 4];
                afl[mt][3] = As_lo[mb + ar + 8][ks + ac + 4];
            }
            uint32_t bfh[2][2], bfl[2][2];
#pragma unroll
            for (int nt = 0; nt < 2; nt++) {
                const int nb = wn + nt * 8;
                bfh[nt][0] = Bs_hi[nb + bc][ks + br    ];
                bfh[nt][1] = Bs_hi[nb + bc][ks + br + 4];
                bfl[nt][0] = Bs_lo[nb + bc][ks + br    ];
                bfl[nt][1] = Bs_lo[nb + bc][ks + br + 4];
            }
#pragma unroll
            for (int mt = 0; mt < 4; mt++)
#pragma unroll
                for (int nt = 0; nt < 2; nt++) {
                    // small terms first, dominant last
                    mma_tf32(acc[mt][nt], afh[mt][0], afh[mt][1], afh[mt][2], afh[mt][3],
                             bfl[nt][0], bfl[nt][1]);
                    mma_tf32(acc[mt][nt], afl[mt][0], afl[mt][1], afl[mt][2], afl[mt][3],
                             bfh[nt][0], bfh[nt][1]);
                    mma_tf32(acc[mt][nt], afh[mt][0], afh[mt][1], afh[mt][2], afh[mt][3],
                             bfh[nt][0], bfh[nt][1]);
                }
        }
        __syncthreads();
    }

    // ---- epilogue ----
    const int cr = lane >> 2;
    const int cc = (lane & 3) * 2;
#pragma unroll
    for (int mt = 0; mt < 4; mt++) {
#pragma unroll
        for (int nt = 0; nt < 2; nt++) {
            const int m = m0 + wm + mt * 16 + cr;
            const int n = n0 + wn + nt * 8 + cc;
            float2 v0, v1;
            v0.x = acc[mt][nt][0]; v0.y = acc[mt][nt][1];
            v1.x = acc[mt][nt][2]; v1.y = acc[mt][nt][3];
            if (BIAS) {
                const float b0 = bias[n], b1 = bias[n + 1];
                v0.x += b0; v0.y += b1;
                v1.x += b0; v1.y += b1;
            }
            *(float2*)(C + (size_t)m       * ldc + n) = v0;
            *(float2*)(C + (size_t)(m + 8) * ldc + n) = v1;
        }
    }
}

// ---------------------------------------------------------------------------
// Per-(qk, head, l) RMSNorm (eps=1e-6, over HD) + RoPE, in place on g_qkv.
// ---------------------------------------------------------------------------
__global__ void norm_rope_kernel(const float* __restrict__ pe,
                                 const float* __restrict__ q_scale,
                                 const float* __restrict__ k_scale)
{
    const int idx = blockIdx.x;
    const int l   = idx & (LQ - 1);
    const int h   = (idx >> 11) & (NH - 1);
    const int qk  = idx >> 15;                  // 0 = q, 1 = k
    const int d   = threadIdx.x;                // 0..127
    const int lane = d & 31, warp = d >> 5;

    float* row = g_qkv + (size_t)l * QKV_N + qk * DIM + h * HD;
    const float t = row[d];

    float ss = t * t;
#pragma unroll
    for (int o = 16; o > 0; o >>= 1) ss += __shfl_xor_sync(0xFFFFFFFFu, ss, o);
    __shared__ float red[4];
    if (lane == 0) red[warp] = ss;
    __syncthreads();
    const float tot = red[0] + red[1] + red[2] + red[3];
    const float rrms = rsqrtf(tot * (1.0f / HD) + 1e-6f);

    const float* scale = qk ? k_scale : q_scale;
    const float tn = t * rrms * scale[d];

    const float other = __shfl_xor_sync(0xFFFFFFFFu, tn, 1);
    const int j = d >> 1, s = d & 1;
    const float* pp = pe + ((size_t)l * (HD / 2) + j) * 4 + s * 2;
    const float te = (s == 0) ? tn : other;
    const float to = (s == 0) ? other : tn;
    row[d] = pp[0] * te + pp[1] * to;
}

// ---------------------------------------------------------------------------
// Row softmax over g_S: 16*2048 rows of 2048, scale 1/sqrt(HD) before exp.
// ---------------------------------------------------------------------------
__global__ void softmax_kernel()
{
    constexpr float SCALE = 0.08838834764831845f;  // 1/sqrt(128)
    float* p = g_S + (size_t)blockIdx.x * LQ;
    const int tid = threadIdx.x;
    const int lane = tid & 31, warp = tid >> 5;
    __shared__ float red[8];

    float v[8];
    float mx = -3.4e38f;
#pragma unroll
    for (int i = 0; i < 8; i++) {
        v[i] = p[tid + i * 256];
        mx = fmaxf(mx, v[i]);
    }
#pragma unroll
    for (int o = 16; o > 0; o >>= 1) mx = fmaxf(mx, __shfl_xor_sync(0xFFFFFFFFu, mx, o));
    if (lane == 0) red[warp] = mx;
    __syncthreads();
    float m = red[0];
#pragma unroll
    for (int i = 1; i < 8; i++) m = fmaxf(m, red[i]);
    __syncthreads();

    float sum = 0.f;
#pragma unroll
    for (int i = 0; i < 8; i++) {
        v[i] = __expf((v[i] - m) * SCALE);
        sum += v[i];
    }
#pragma unroll
    for (int o = 16; o > 0; o >>= 1) sum += __shfl_xor_sync(0xFFFFFFFFu, sum, o);
    if (lane == 0) red[warp] = sum;
    __syncthreads();
    float tot = red[0];
#pragma unroll
    for (int i = 1; i < 8; i++) tot += red[i];
    const float inv = 1.0f / tot;

#pragma unroll
    for (int i = 0; i < 8; i++) p[tid + i * 256] = v[i] * inv;
}

// ---------------------------------------------------------------------------
// Launch
// ---------------------------------------------------------------------------
extern "C" void kernel_launch(void* const* d_in, const int* in_sizes, int n_in,
                              void* d_out, int out_size)
{
    const float* x       = (const float*)d_in[0];
    const float* pe      = (const float*)d_in[1];
    const float* qkv_w   = (const float*)d_in[2];
    const float* q_scale = (const float*)d_in[3];
    const float* k_scale = (const float*)d_in[4];
    const float* proj_w  = (const float*)d_in[5];
    const float* proj_b  = (const float*)d_in[6];
    float* out = (float*)d_out;

    float *qkv, *S, *att;
    cudaGetSymbolAddress((void**)&qkv, g_qkv);
    cudaGetSymbolAddress((void**)&S,   g_S);
    cudaGetSymbolAddress((void**)&att, g_att);

    // 1) qkv = x @ qkv_w^T          [2048, 6144]
    {
        dim3 grid(QKV_N / 64, LQ / 128, 1);
        mma_gemm<true, false><<<grid, 256>>>(
            x, qkv_w, qkv, nullptr,
            LQ, QKV_N, DIM, DIM, DIM, QKV_N, 0, 0, 0);
    }

    // 2) per-head RMSNorm + RoPE on q and k (in place)
    norm_rope_kernel<<<2 * NH * LQ, 128>>>(pe, q_scale, k_scale);

    // 3) S_h = Q_h @ K_h^T (scale folded into softmax)
    {
        dim3 grid(LQ / 64, LQ / 128, NH);
        mma_gemm<true, false><<<grid, 256>>>(
            qkv, qkv + DIM, S, nullptr,
            LQ, LQ, HD, QKV_N, QKV_N, LQ,
            /*sA=*/HD, /*sB=*/HD, /*sC=*/(long)LQ * LQ);
    }

    // 4) softmax rows
    softmax_kernel<<<NH * LQ, 256>>>();

    // 5) att_h = P_h @ V_h
    {
        dim3 grid(HD / 64, LQ / 128, NH);
        mma_gemm<false, false><<<grid, 256>>>(
            S, qkv + 2 * DIM, att, nullptr,
            LQ, HD, LQ, LQ, QKV_N, DIM,
            /*sA=*/(long)LQ * LQ, /*sB=*/HD, /*sC=*/HD);
    }

    // 6) out = att @ proj_w^T + proj_b
    {
        dim3 grid(DIM / 64, LQ / 128, 1);
        mma_gemm<true, true><<<grid, 256>>>(
            att, proj_w, out, proj_b,
            LQ, DIM, DIM, DIM, DIM, DIM, 0, 0, 0);
    }
}

// round 8
// speedup vs baseline: 1.9258x; 1.8251x over previous
#include <cuda_runtime.h>
#include <cuda_bf16.h>
#include <cstdint>

// ---------------------------------------------------------------------------
// Problem constants (fixed shapes)
// ---------------------------------------------------------------------------
#define LQ   2048      // sequence length
#define DIM  2048
#define NH   16        // heads
#define HD   128       // head dim
#define QKV_N (3*DIM)  // 6144

// Scratch (allocation-free rule: __device__ globals)
__device__ float g_qkv[(size_t)LQ * QKV_N];   // [L, 6144]  q|k|v per row
__device__ float g_S  [(size_t)NH * LQ * LQ]; // [H, L, L]  scores / probs
__device__ float g_att[(size_t)LQ * DIM];     // [L, H*HD]

// ---------------------------------------------------------------------------
// bf16 split helpers: f = hi + lo, each bf16; dropped lo*lo ~ 2^-18
// ---------------------------------------------------------------------------
__device__ __forceinline__ void split_bf16(float f, __nv_bfloat16& h, __nv_bfloat16& l) {
    h = __float2bfloat16_rn(f);
    l = __float2bfloat16_rn(f - __bfloat162float(h));
}

// pack two (hi,lo) splits of consecutive elements into bf16x2 words (elem0 in low half)
__device__ __forceinline__ void split2_bf16(float x, float y, uint32_t& hw, uint32_t& lw) {
    __nv_bfloat16 hx, lx, hy, ly;
    split_bf16(x, hx, lx);
    split_bf16(y, hy, ly);
    __nv_bfloat162 hp, lp;
    hp.x = hx; hp.y = hy;
    lp.x = lx; lp.y = ly;
    hw = *(uint32_t*)&hp;
    lw = *(uint32_t*)&lp;
}

__device__ __forceinline__ void mma_bf16(float c[4],
                                         uint32_t a0, uint32_t a1, uint32_t a2, uint32_t a3,
                                         uint32_t b0, uint32_t b1) {
    asm volatile(
        "mma.sync.aligned.m16n8k16.row.col.f32.bf16.bf16.f32 "
        "{%0,%1,%2,%3}, {%4,%5,%6,%7}, {%8,%9}, {%0,%1,%2,%3};"
        : "+f"(c[0]), "+f"(c[1]), "+f"(c[2]), "+f"(c[3])
        : "r"(a0), "r"(a1), "r"(a2), "r"(a3), "r"(b0), "r"(b1));
}

// ---------------------------------------------------------------------------
// bf16x3 tensor-core GEMM (fp32-accurate): C = A @ B(^T) (+bias)
//   TRANS_B=true : B row-major [N,K]  => A @ B^T
//   TRANS_B=false: B row-major [K,N]  => A @ B
// CTA tile 128x64x32, 8 warps (2x4), warp tile 64x16 (4x2 m16n8 frags),
// m16n8k16 bf16 MMAs, product = hi*lo + lo*hi + hi*hi (3 MMAs).
// Smem stores bf16x2 pairs along k: As[m][kpair], stride 20 (conflict-free).
// Batched over blockIdx.z (element strides sA/sB/sC).
// Requires M%128==0, N%64==0, K%32==0, 16B-aligned rows.
// ---------------------------------------------------------------------------
template<bool TRANS_B, bool BIAS>
__global__ __launch_bounds__(256, 2)
void mma_gemm(const float* __restrict__ Ag, const float* __restrict__ Bg,
              float* __restrict__ Cg, const float* __restrict__ bias,
              int M, int N, int K, int lda, int ldb, int ldc,
              long sA, long sB, long sC)
{
    constexpr int BM = 128, BN = 64, BK = 32;
    constexpr int KP = BK / 2;         // 16 k-pairs
    constexpr int KPP = KP + 4;        // padded stride 20 (bank permutation)

    __shared__ uint32_t As_hi[BM][KPP], As_lo[BM][KPP];
    __shared__ uint32_t Bs_hi[BN][KPP], Bs_lo[BN][KPP];

    const int tid  = threadIdx.x;
    const int warp = tid >> 5;
    const int lane = tid & 31;
    const int wm   = (warp >> 2) * 64;   // warp m-origin
    const int wn   = (warp & 3) * 16;    // warp n-origin
    const int m0   = blockIdx.y * BM;
    const int n0   = blockIdx.x * BN;

    const float* A = Ag + (size_t)blockIdx.z * sA;
    const float* B = Bg + (size_t)blockIdx.z * sB;
    float*       C = Cg + (size_t)blockIdx.z * sC;

    float acc[4][2][4];
#pragma unroll
    for (int i = 0; i < 4; i++)
#pragma unroll
        for (int j = 0; j < 2; j++)
#pragma unroll
            for (int r = 0; r < 4; r++) acc[i][j][r] = 0.f;

    const int ar = lane >> 2, ac = lane & 3;   // A-frag row / k-pair
    const int br = lane & 3,  bc = lane >> 2;  // B-frag k-pair / n

    for (int k0 = 0; k0 < K; k0 += BK) {
        // ---- stage A tile [BM x BK] -> As_{hi,lo}[m][kpair] (4 float4/thread) ----
#pragma unroll
        for (int i = tid; i < BM * BK / 4; i += 256) {
            const int m  = i >> 3;             // 8 float4 per row
            const int q  = (i & 7) << 2;       // k offset (elems)
            const float4 v = *(const float4*)(A + (size_t)(m0 + m) * lda + k0 + q);
            uint32_t h01, l01, h23, l23;
            split2_bf16(v.x, v.y, h01, l01);
            split2_bf16(v.z, v.w, h23, l23);
            const int p = q >> 1;
            uint2 th = {h01, h23}, tl = {l01, l23};
            *(uint2*)&As_hi[m][p] = th;
            *(uint2*)&As_lo[m][p] = tl;
        }
        // ---- stage B tile -> Bs_{hi,lo}[n][kpair] ----
        if (TRANS_B) {
#pragma unroll
            for (int i = tid; i < BN * BK / 4; i += 256) {
                const int n = i >> 3;
                const int q = (i & 7) << 2;
                const float4 v = *(const float4*)(B + (size_t)(n0 + n) * ldb + k0 + q);
                uint32_t h01, l01, h23, l23;
                split2_bf16(v.x, v.y, h01, l01);
                split2_bf16(v.z, v.w, h23, l23);
                const int p = q >> 1;
                uint2 th = {h01, h23}, tl = {l01, l23};
                *(uint2*)&Bs_hi[n][p] = th;
                *(uint2*)&Bs_lo[n][p] = tl;
            }
        } else {
            // B row-major [K,N]: element (k, n) -> halfword (k&1) of Bs[n][k>>1]
#pragma unroll
            for (int i = tid; i < BK * BN / 4; i += 256) {
                const int kk = i >> 4;           // 0..31
                const int nq = (i & 15) << 2;    // 0..60
                const float4 v = *(const float4*)(B + (size_t)(k0 + kk) * ldb + n0 + nq);
                const int p = kk >> 1, s = kk & 1;
                __nv_bfloat16 h, l;
                split_bf16(v.x, h, l);
                ((__nv_bfloat16*)&Bs_hi[nq + 0][p])[s] = h;
                ((__nv_bfloat16*)&Bs_lo[nq + 0][p])[s] = l;
                split_bf16(v.y, h, l);
                ((__nv_bfloat16*)&Bs_hi[nq + 1][p])[s] = h;
                ((__nv_bfloat16*)&Bs_lo[nq + 1][p])[s] = l;
                split_bf16(v.z, h, l);
                ((__nv_bfloat16*)&Bs_hi[nq + 2][p])[s] = h;
                ((__nv_bfloat16*)&Bs_lo[nq + 2][p])[s] = l;
                split_bf16(v.w, h, l);
                ((__nv_bfloat16*)&Bs_hi[nq + 3][p])[s] = h;
                ((__nv_bfloat16*)&Bs_lo[nq + 3][p])[s] = l;
            }
        }
        __syncthreads();

        // ---- compute: 2 k16-steps, bf16x3 per step ----
#pragma unroll
        for (int kc = 0; kc < KP; kc += 8) {     // kc in k-pair units
            uint32_t afh[4][4], afl[4][4];
#pragma unroll
            for (int mt = 0; mt < 4; mt++) {
                const int mb = wm + mt * 16;
                afh[mt][0] = As_hi[mb + ar    ][kc + ac    ];
                afh[mt][1] = As_hi[mb + ar + 8][kc + ac    ];
                afh[mt][2] = As_hi[mb + ar    ][kc + ac + 4];
                afh[mt][3] = As_hi[mb + ar + 8][kc + ac + 4];
                afl[mt][0] = As_lo[mb + ar    ][kc + ac    ];
                afl[mt][1] = As_lo[mb + ar + 8][kc + ac    ];
                afl[mt][2] = As_lo[mb + ar    ][kc + ac + 4];
                afl[mt][3] = As_lo[mb + ar + 8][kc + ac + 4];
            }
            uint32_t bfh[2][2], bfl[2][2];
#pragma unroll
            for (int nt = 0; nt < 2; nt++) {
                const int nb = wn + nt * 8;
                bfh[nt][0] = Bs_hi[nb + bc][kc + br    ];
                bfh[nt][1] = Bs_hi[nb + bc][kc + br + 4];
                bfl[nt][0] = Bs_lo[nb + bc][kc + br    ];
                bfl[nt][1] = Bs_lo[nb + bc][kc + br + 4];
            }
#pragma unroll
            for (int mt = 0; mt < 4; mt++)
#pragma unroll
                for (int nt = 0; nt < 2; nt++) {
                    // small terms first, dominant last
                    mma_bf16(acc[mt][nt], afh[mt][0], afh[mt][1], afh[mt][2], afh[mt][3],
                             bfl[nt][0], bfl[nt][1]);
                    mma_bf16(acc[mt][nt], afl[mt][0], afl[mt][1], afl[mt][2], afl[mt][3],
                             bfh[nt][0], bfh[nt][1]);
                    mma_bf16(acc[mt][nt], afh[mt][0], afh[mt][1], afh[mt][2], afh[mt][3],
                             bfh[nt][0], bfh[nt][1]);
                }
        }
        __syncthreads();
    }

    // ---- epilogue ----
    const int cr = lane >> 2;
    const int cc = (lane & 3) * 2;
#pragma unroll
    for (int mt = 0; mt < 4; mt++) {
#pragma unroll
        for (int nt = 0; nt < 2; nt++) {
            const int m = m0 + wm + mt * 16 + cr;
            const int n = n0 + wn + nt * 8 + cc;
            float2 v0, v1;
            v0.x = acc[mt][nt][0]; v0.y = acc[mt][nt][1];
            v1.x = acc[mt][nt][2]; v1.y = acc[mt][nt][3];
            if (BIAS) {
                const float b0 = bias[n], b1 = bias[n + 1];
                v0.x += b0; v0.y += b1;
                v1.x += b0; v1.y += b1;
            }
            *(float2*)(C + (size_t)m       * ldc + n) = v0;
            *(float2*)(C + (size_t)(m + 8) * ldc + n) = v1;
        }
    }
}

// ---------------------------------------------------------------------------
// Per-(qk, head, l) RMSNorm (eps=1e-6, over HD) + RoPE, in place on g_qkv.
// ---------------------------------------------------------------------------
__global__ void norm_rope_kernel(const float* __restrict__ pe,
                                 const float* __restrict__ q_scale,
                                 const float* __restrict__ k_scale)
{
    const int idx = blockIdx.x;
    const int l   = idx & (LQ - 1);
    const int h   = (idx >> 11) & (NH - 1);
    const int qk  = idx >> 15;                  // 0 = q, 1 = k
    const int d   = threadIdx.x;                // 0..127
    const int lane = d & 31, warp = d >> 5;

    float* row = g_qkv + (size_t)l * QKV_N + qk * DIM + h * HD;
    const float t = row[d];

    float ss = t * t;
#pragma unroll
    for (int o = 16; o > 0; o >>= 1) ss += __shfl_xor_sync(0xFFFFFFFFu, ss, o);
    __shared__ float red[4];
    if (lane == 0) red[warp] = ss;
    __syncthreads();
    const float tot = red[0] + red[1] + red[2] + red[3];
    const float rrms = rsqrtf(tot * (1.0f / HD) + 1e-6f);

    const float* scale = qk ? k_scale : q_scale;
    const float tn = t * rrms * scale[d];

    const float other = __shfl_xor_sync(0xFFFFFFFFu, tn, 1);
    const int j = d >> 1, s = d & 1;
    const float* pp = pe + ((size_t)l * (HD / 2) + j) * 4 + s * 2;
    const float te = (s == 0) ? tn : other;
    const float to = (s == 0) ? other : tn;
    row[d] = pp[0] * te + pp[1] * to;
}

// ---------------------------------------------------------------------------
// Row softmax over g_S: 16*2048 rows of 2048, scale 1/sqrt(HD) before exp.
// ---------------------------------------------------------------------------
__global__ void softmax_kernel()
{
    constexpr float SCALE = 0.08838834764831845f;  // 1/sqrt(128)
    float* p = g_S + (size_t)blockIdx.x * LQ;
    const int tid = threadIdx.x;
    const int lane = tid & 31, warp = tid >> 5;
    __shared__ float red[8];

    float v[8];
    float mx = -3.4e38f;
#pragma unroll
    for (int i = 0; i < 8; i++) {
        v[i] = p[tid + i * 256];
        mx = fmaxf(mx, v[i]);
    }
#pragma unroll
    for (int o = 16; o > 0; o >>= 1) mx = fmaxf(mx, __shfl_xor_sync(0xFFFFFFFFu, mx, o));
    if (lane == 0) red[warp] = mx;
    __syncthreads();
    float m = red[0];
#pragma unroll
    for (int i = 1; i < 8; i++) m = fmaxf(m, red[i]);
    __syncthreads();

    float sum = 0.f;
#pragma unroll
    for (int i = 0; i < 8; i++) {
        v[i] = __expf((v[i] - m) * SCALE);
        sum += v[i];
    }
#pragma unroll
    for (int o = 16; o > 0; o >>= 1) sum += __shfl_xor_sync(0xFFFFFFFFu, sum, o);
    if (lane == 0) red[warp] = sum;
    __syncthreads();
    float tot = red[0];
#pragma unroll
    for (int i = 1; i < 8; i++) tot += red[i];
    const float inv = 1.0f / tot;

#pragma unroll
    for (int i = 0; i < 8; i++) p[tid + i * 256] = v[i] * inv;
}

// ---------------------------------------------------------------------------
// Launch
// ---------------------------------------------------------------------------
extern "C" void kernel_launch(void* const* d_in, const int* in_sizes, int n_in,
                              void* d_out, int out_size)
{
    const float* x       = (const float*)d_in[0];
    const float* pe      = (const float*)d_in[1];
    const float* qkv_w   = (const float*)d_in[2];
    const float* q_scale = (const float*)d_in[3];
    const float* k_scale = (const float*)d_in[4];
    const float* proj_w  = (const float*)d_in[5];
    const float* proj_b  = (const float*)d_in[6];
    float* out = (float*)d_out;

    float *qkv, *S, *att;
    cudaGetSymbolAddress((void**)&qkv, g_qkv);
    cudaGetSymbolAddress((void**)&S,   g_S);
    cudaGetSymbolAddress((void**)&att, g_att);

    // 1) qkv = x @ qkv_w^T          [2048, 6144]
    {
        dim3 grid(QKV_N / 64, LQ / 128, 1);
        mma_gemm<true, false><<<grid, 256>>>(
            x, qkv_w, qkv, nullptr,
            LQ, QKV_N, DIM, DIM, DIM, QKV_N, 0, 0, 0);
    }

    // 2) per-head RMSNorm + RoPE on q and k (in place)
    norm_rope_kernel<<<2 * NH * LQ, 128>>>(pe, q_scale, k_scale);

    // 3) S_h = Q_h @ K_h^T (scale folded into softmax)
    {
        dim3 grid(LQ / 64, LQ / 128, NH);
        mma_gemm<true, false><<<grid, 256>>>(
            qkv, qkv + DIM, S, nullptr,
            LQ, LQ, HD, QKV_N, QKV_N, LQ,
            /*sA=*/HD, /*sB=*/HD, /*sC=*/(long)LQ * LQ);
    }

    // 4) softmax rows
    softmax_kernel<<<NH * LQ, 256>>>();

    // 5) att_h = P_h @ V_h
    {
        dim3 grid(HD / 64, LQ / 128, NH);
        mma_gemm<false, false><<<grid, 256>>>(
            S, qkv + 2 * DIM, att, nullptr,
            LQ, HD, LQ, LQ, QKV_N, DIM,
            /*sA=*/(long)LQ * LQ, /*sB=*/HD, /*sC=*/HD);
    }

    // 6) out = att @ proj_w^T + proj_b
    {
        dim3 grid(DIM / 64, LQ / 128, 1);
        mma_gemm<true, true><<<grid, 256>>>(
            att, proj_w, out, proj_b,
            LQ, DIM, DIM, DIM, DIM, DIM, 0, 0, 0);
    }
}

// round 9
// speedup vs baseline: 2.1755x; 1.1297x over previous
#include <cuda_runtime.h>
#include <cuda_bf16.h>
#include <cstdint>

// ---------------------------------------------------------------------------
// Problem constants (fixed shapes)
// ---------------------------------------------------------------------------
#define LQ   2048      // sequence length
#define DIM  2048
#define NH   16        // heads
#define HD   128       // head dim
#define QKV_N (3*DIM)  // 6144

// Scratch (allocation-free rule: __device__ globals)
__device__ float g_qkv[(size_t)LQ * QKV_N];   // [L, 6144]  q|k|v per row
__device__ float g_S  [(size_t)NH * LQ * LQ]; // [H, L, L]  scores / probs
__device__ float g_att[(size_t)LQ * DIM];     // [L, H*HD]

// ---------------------------------------------------------------------------
// bf16 split helpers: f = hi + lo, each bf16; dropped lo*lo ~ 2^-18
// ---------------------------------------------------------------------------
__device__ __forceinline__ void split_bf16(float f, __nv_bfloat16& h, __nv_bfloat16& l) {
    h = __float2bfloat16_rn(f);
    l = __float2bfloat16_rn(f - __bfloat162float(h));
}

// pack (hi,lo) of two k-consecutive elements into bf16x2 words (elem0 low half)
__device__ __forceinline__ void split2_bf16(float x, float y, uint32_t& hw, uint32_t& lw) {
    __nv_bfloat16 hx, lx, hy, ly;
    split_bf16(x, hx, lx);
    split_bf16(y, hy, ly);
    __nv_bfloat162 hp, lp;
    hp.x = hx; hp.y = hy;
    lp.x = lx; lp.y = ly;
    hw = *(uint32_t*)&hp;
    lw = *(uint32_t*)&lp;
}

__device__ __forceinline__ void mma_bf16(float c[4],
                                         uint32_t a0, uint32_t a1, uint32_t a2, uint32_t a3,
                                         uint32_t b0, uint32_t b1) {
    asm volatile(
        "mma.sync.aligned.m16n8k16.row.col.f32.bf16.bf16.f32 "
        "{%0,%1,%2,%3}, {%4,%5,%6,%7}, {%8,%9}, {%0,%1,%2,%3};"
        : "+f"(c[0]), "+f"(c[1]), "+f"(c[2]), "+f"(c[3])
        : "r"(a0), "r"(a1), "r"(a2), "r"(a3), "r"(b0), "r"(b1));
}

// ---------------------------------------------------------------------------
// bf16x3 tensor-core GEMM (fp32-accurate): C = A @ B(^T) (+bias)
//   TRANS_B=true : B row-major [N,K]  => A @ B^T
//   TRANS_B=false: B row-major [K,N]  => A @ B
// CTA tile 128x128x32, 8 warps (2x4), warp tile 64x32 (4x4 m16n8 frags),
// m16n8k16 bf16 MMAs, product = hi*lo + lo*hi + hi*hi (3 MMAs).
// Smem stores bf16x2 k-pairs: As[m][kpair], stride 20 u32 (bank permutation).
// Batched over blockIdx.z (element strides sA/sB/sC).
// Requires M%128==0, N%128==0, K%32==0, 16B-aligned rows.
// ---------------------------------------------------------------------------
template<bool TRANS_B, bool BIAS>
__global__ __launch_bounds__(256, 2)
void mma_gemm(const float* __restrict__ Ag, const float* __restrict__ Bg,
              float* __restrict__ Cg, const float* __restrict__ bias,
              int M, int N, int K, int lda, int ldb, int ldc,
              long sA, long sB, long sC)
{
    constexpr int BM = 128, BN = 128, BK = 32;
    constexpr int KP  = BK / 2;     // 16 k-pairs
    constexpr int KPP = KP + 4;     // stride 20 u32

    __shared__ uint32_t As_hi[BM][KPP], As_lo[BM][KPP];
    __shared__ uint32_t Bs_hi[BN][KPP], Bs_lo[BN][KPP];

    const int tid  = threadIdx.x;
    const int warp = tid >> 5;
    const int lane = tid & 31;
    const int wm   = (warp >> 2) * 64;   // warp m-origin
    const int wn   = (warp & 3) * 32;    // warp n-origin
    const int m0   = blockIdx.y * BM;
    const int n0   = blockIdx.x * BN;

    const float* A = Ag + (size_t)blockIdx.z * sA;
    const float* B = Bg + (size_t)blockIdx.z * sB;
    float*       C = Cg + (size_t)blockIdx.z * sC;

    float acc[4][4][4];
#pragma unroll
    for (int i = 0; i < 4; i++)
#pragma unroll
        for (int j = 0; j < 4; j++)
#pragma unroll
            for (int r = 0; r < 4; r++) acc[i][j][r] = 0.f;

    const int ar = lane >> 2, ac = lane & 3;   // A-frag row / k-pair
    const int br = lane & 3,  bc = lane >> 2;  // B-frag k-pair / n

    for (int k0 = 0; k0 < K; k0 += BK) {
        // ---- stage A tile [BM x BK] -> As_{hi,lo}[m][kpair] ----
#pragma unroll
        for (int i = tid; i < BM * BK / 4; i += 256) {
            const int m = i >> 3;              // 8 float4 per row
            const int q = (i & 7) << 2;        // k offset (elems)
            const float4 v = *(const float4*)(A + (size_t)(m0 + m) * lda + k0 + q);
            uint32_t h01, l01, h23, l23;
            split2_bf16(v.x, v.y, h01, l01);
            split2_bf16(v.z, v.w, h23, l23);
            const int p = q >> 1;
            uint2 th = {h01, h23}, tl = {l01, l23};
            *(uint2*)&As_hi[m][p] = th;
            *(uint2*)&As_lo[m][p] = tl;
        }
        // ---- stage B tile -> Bs_{hi,lo}[n][kpair] ----
        if (TRANS_B) {
#pragma unroll
            for (int i = tid; i < BN * BK / 4; i += 256) {
                const int n = i >> 3;
                const int q = (i & 7) << 2;
                const float4 v = *(const float4*)(B + (size_t)(n0 + n) * ldb + k0 + q);
                uint32_t h01, l01, h23, l23;
                split2_bf16(v.x, v.y, h01, l01);
                split2_bf16(v.z, v.w, h23, l23);
                const int p = q >> 1;
                uint2 th = {h01, h23}, tl = {l01, l23};
                *(uint2*)&Bs_hi[n][p] = th;
                *(uint2*)&Bs_lo[n][p] = tl;
            }
        } else {
            // B row-major [K,N]: load two k-rows, pack k-pairs, 32-bit stores
#pragma unroll
            for (int i = tid; i < (BK / 2) * (BN / 4); i += 256) {
                const int kk2 = i >> 5;            // k-pair index 0..15
                const int nq  = (i & 31) << 2;     // 0..124
                const float* r0 = B + (size_t)(k0 + 2 * kk2)     * ldb + n0 + nq;
                const float* r1 = B + (size_t)(k0 + 2 * kk2 + 1) * ldb + n0 + nq;
                const float4 v0 = *(const float4*)r0;
                const float4 v1 = *(const float4*)r1;
                uint32_t hw, lw;
                split2_bf16(v0.x, v1.x, hw, lw); Bs_hi[nq + 0][kk2] = hw; Bs_lo[nq + 0][kk2] = lw;
                split2_bf16(v0.y, v1.y, hw, lw); Bs_hi[nq + 1][kk2] = hw; Bs_lo[nq + 1][kk2] = lw;
                split2_bf16(v0.z, v1.z, hw, lw); Bs_hi[nq + 2][kk2] = hw; Bs_lo[nq + 2][kk2] = lw;
                split2_bf16(v0.w, v1.w, hw, lw); Bs_hi[nq + 3][kk2] = hw; Bs_lo[nq + 3][kk2] = lw;
            }
        }
        __syncthreads();

        // ---- compute: 2 k16-steps, bf16x3 per step ----
#pragma unroll
        for (int kc = 0; kc < KP; kc += 8) {       // kc in k-pair units
            // B fragments persistent for this k-step
            uint32_t bfh[4][2], bfl[4][2];
#pragma unroll
            for (int nt = 0; nt < 4; nt++) {
                const int nb = wn + nt * 8;
                bfh[nt][0] = Bs_hi[nb + bc][kc + br    ];
                bfh[nt][1] = Bs_hi[nb + bc][kc + br + 4];
                bfl[nt][0] = Bs_lo[nb + bc][kc + br    ];
                bfl[nt][1] = Bs_lo[nb + bc][kc + br + 4];
            }
            // A fragments per mt (keeps register live-range small)
#pragma unroll
            for (int mt = 0; mt < 4; mt++) {
                const int mb = wm + mt * 16;
                uint32_t ah0 = As_hi[mb + ar    ][kc + ac    ];
                uint32_t ah1 = As_hi[mb + ar + 8][kc + ac    ];
                uint32_t ah2 = As_hi[mb + ar    ][kc + ac + 4];
                uint32_t ah3 = As_hi[mb + ar + 8][kc + ac + 4];
                uint32_t al0 = As_lo[mb + ar    ][kc + ac    ];
                uint32_t al1 = As_lo[mb + ar + 8][kc + ac    ];
                uint32_t al2 = As_lo[mb + ar    ][kc + ac + 4];
                uint32_t al3 = As_lo[mb + ar + 8][kc + ac + 4];
#pragma unroll
                for (int nt = 0; nt < 4; nt++) {
                    mma_bf16(acc[mt][nt], ah0, ah1, ah2, ah3, bfl[nt][0], bfl[nt][1]);
                    mma_bf16(acc[mt][nt], al0, al1, al2, al3, bfh[nt][0], bfh[nt][1]);
                    mma_bf16(acc[mt][nt], ah0, ah1, ah2, ah3, bfh[nt][0], bfh[nt][1]);
                }
            }
        }
        __syncthreads();
    }

    // ---- epilogue ----
    const int cr = lane >> 2;
    const int cc = (lane & 3) * 2;
#pragma unroll
    for (int mt = 0; mt < 4; mt++) {
#pragma unroll
        for (int nt = 0; nt < 4; nt++) {
            const int m = m0 + wm + mt * 16 + cr;
            const int n = n0 + wn + nt * 8 + cc;
            float2 v0, v1;
            v0.x = acc[mt][nt][0]; v0.y = acc[mt][nt][1];
            v1.x = acc[mt][nt][2]; v1.y = acc[mt][nt][3];
            if (BIAS) {
                const float b0 = bias[n], b1 = bias[n + 1];
                v0.x += b0; v0.y += b1;
                v1.x += b0; v1.y += b1;
            }
            *(float2*)(C + (size_t)m       * ldc + n) = v0;
            *(float2*)(C + (size_t)(m + 8) * ldc + n) = v1;
        }
    }
}

// ---------------------------------------------------------------------------
// Per-(qk, head, l) RMSNorm (eps=1e-6, over HD) + RoPE, in place on g_qkv.
// ---------------------------------------------------------------------------
__global__ void norm_rope_kernel(const float* __restrict__ pe,
                                 const float* __restrict__ q_scale,
                                 const float* __restrict__ k_scale)
{
    const int idx = blockIdx.x;
    const int l   = idx & (LQ - 1);
    const int h   = (idx >> 11) & (NH - 1);
    const int qk  = idx >> 15;                  // 0 = q, 1 = k
    const int d   = threadIdx.x;                // 0..127
    const int lane = d & 31, warp = d >> 5;

    float* row = g_qkv + (size_t)l * QKV_N + qk * DIM + h * HD;
    const float t = row[d];

    float ss = t * t;
#pragma unroll
    for (int o = 16; o > 0; o >>= 1) ss += __shfl_xor_sync(0xFFFFFFFFu, ss, o);
    __shared__ float red[4];
    if (lane == 0) red[warp] = ss;
    __syncthreads();
    const float tot = red[0] + red[1] + red[2] + red[3];
    const float rrms = rsqrtf(tot * (1.0f / HD) + 1e-6f);

    const float* scale = qk ? k_scale : q_scale;
    const float tn = t * rrms * scale[d];

    const float other = __shfl_xor_sync(0xFFFFFFFFu, tn, 1);
    const int j = d >> 1, s = d & 1;
    const float* pp = pe + ((size_t)l * (HD / 2) + j) * 4 + s * 2;
    const float te = (s == 0) ? tn : other;
    const float to = (s == 0) ? other : tn;
    row[d] = pp[0] * te + pp[1] * to;
}

// ---------------------------------------------------------------------------
// Row softmax over g_S: 16*2048 rows of 2048, scale 1/sqrt(HD) before exp.
// ---------------------------------------------------------------------------
__global__ void softmax_kernel()
{
    constexpr float SCALE = 0.08838834764831845f;  // 1/sqrt(128)
    float* p = g_S + (size_t)blockIdx.x * LQ;
    const int tid = threadIdx.x;
    const int lane = tid & 31, warp = tid >> 5;
    __shared__ float red[8];

    float v[8];
    float mx = -3.4e38f;
#pragma unroll
    for (int i = 0; i < 8; i++) {
        v[i] = p[tid + i * 256];
        mx = fmaxf(mx, v[i]);
    }
#pragma unroll
    for (int o = 16; o > 0; o >>= 1) mx = fmaxf(mx, __shfl_xor_sync(0xFFFFFFFFu, mx, o));
    if (lane == 0) red[warp] = mx;
    __syncthreads();
    float m = red[0];
#pragma unroll
    for (int i = 1; i < 8; i++) m = fmaxf(m, red[i]);
    __syncthreads();

    float sum = 0.f;
#pragma unroll
    for (int i = 0; i < 8; i++) {
        v[i] = __expf((v[i] - m) * SCALE);
        sum += v[i];
    }
#pragma unroll
    for (int o = 16; o > 0; o >>= 1) sum += __shfl_xor_sync(0xFFFFFFFFu, sum, o);
    if (lane == 0) red[warp] = sum;
    __syncthreads();
    float tot = red[0];
#pragma unroll
    for (int i = 1; i < 8; i++) tot += red[i];
    const float inv = 1.0f / tot;

#pragma unroll
    for (int i = 0; i < 8; i++) p[tid + i * 256] = v[i] * inv;
}

// ---------------------------------------------------------------------------
// Launch
// ---------------------------------------------------------------------------
extern "C" void kernel_launch(void* const* d_in, const int* in_sizes, int n_in,
                              void* d_out, int out_size)
{
    const float* x       = (const float*)d_in[0];
    const float* pe      = (const float*)d_in[1];
    const float* qkv_w   = (const float*)d_in[2];
    const float* q_scale = (const float*)d_in[3];
    const float* k_scale = (const float*)d_in[4];
    const float* proj_w  = (const float*)d_in[5];
    const float* proj_b  = (const float*)d_in[6];
    float* out = (float*)d_out;

    float *qkv, *S, *att;
    cudaGetSymbolAddress((void**)&qkv, g_qkv);
    cudaGetSymbolAddress((void**)&S,   g_S);
    cudaGetSymbolAddress((void**)&att, g_att);

    // 1) qkv = x @ qkv_w^T          [2048, 6144]
    {
        dim3 grid(QKV_N / 128, LQ / 128, 1);
        mma_gemm<true, false><<<grid, 256>>>(
            x, qkv_w, qkv, nullptr,
            LQ, QKV_N, DIM, DIM, DIM, QKV_N, 0, 0, 0);
    }

    // 2) per-head RMSNorm + RoPE on q and k (in place)
    norm_rope_kernel<<<2 * NH * LQ, 128>>>(pe, q_scale, k_scale);

    // 3) S_h = Q_h @ K_h^T (scale folded into softmax)
    {
        dim3 grid(LQ / 128, LQ / 128, NH);
        mma_gemm<true, false><<<grid, 256>>>(
            qkv, qkv + DIM, S, nullptr,
            LQ, LQ, HD, QKV_N, QKV_N, LQ,
            /*sA=*/HD, /*sB=*/HD, /*sC=*/(long)LQ * LQ);
    }

    // 4) softmax rows
    softmax_kernel<<<NH * LQ, 256>>>();

    // 5) att_h = P_h @ V_h
    {
        dim3 grid(HD / 128, LQ / 128, NH);
        mma_gemm<false, false><<<grid, 256>>>(
            S, qkv + 2 * DIM, att, nullptr,
            LQ, HD, LQ, LQ, QKV_N, DIM,
            /*sA=*/(long)LQ * LQ, /*sB=*/HD, /*sC=*/HD);
    }

    // 6) out = att @ proj_w^T + proj_b
    {
        dim3 grid(DIM / 128, LQ / 128, 1);
        mma_gemm<true, true><<<grid, 256>>>(
            att, proj_w, out, proj_b,
            LQ, DIM, DIM, DIM, DIM, DIM, 0, 0, 0);
    }
}

// round 10
// speedup vs baseline: 2.7656x; 1.2712x over previous
#include <cuda_runtime.h>
#include <cuda_bf16.h>
#include <cuda_fp16.h>
#include <cstdint>

// ---------------------------------------------------------------------------
#define LQ    2048
#define DIM   2048
#define NH    16
#define HD    128
#define QKV_N 6144
#define SCALE 0.08838834764831845f   // 1/sqrt(128)

// ---------------------------------------------------------------------------
// Scratch (__device__ globals; allocation-free rule)
// ---------------------------------------------------------------------------
__device__ float g_qkv[(size_t)LQ * QKV_N];                         // fp32 qkv
__device__ __nv_bfloat16 g_xh[(size_t)LQ * DIM],  g_xl[(size_t)LQ * DIM];
__device__ __nv_bfloat16 g_wh[(size_t)QKV_N * DIM], g_wl[(size_t)QKV_N * DIM];
__device__ __nv_bfloat16 g_pwh[(size_t)DIM * DIM],  g_pwl[(size_t)DIM * DIM];
__device__ __nv_bfloat16 g_qh[(size_t)LQ * DIM],  g_ql[(size_t)LQ * DIM];
__device__ __nv_bfloat16 g_kh[(size_t)LQ * DIM],  g_kl[(size_t)LQ * DIM];
__device__ __half        g_vt[(size_t)DIM * LQ];                     // V^T: [h*128+d][L] fp16
__device__ __nv_bfloat16 g_ah[(size_t)LQ * DIM],  g_al[(size_t)LQ * DIM];

// ---------------------------------------------------------------------------
// helpers
// ---------------------------------------------------------------------------
__device__ __forceinline__ void split_bf16(float f, __nv_bfloat16& h, __nv_bfloat16& l) {
    h = __float2bfloat16_rn(f);
    l = __float2bfloat16_rn(f - __bfloat162float(h));
}
__device__ __forceinline__ void split2_bf16(float x, float y, uint32_t& hw, uint32_t& lw) {
    __nv_bfloat16 hx, lx, hy, ly;
    split_bf16(x, hx, lx);
    split_bf16(y, hy, ly);
    __nv_bfloat162 hp, lp;
    hp.x = hx; hp.y = hy;
    lp.x = lx; lp.y = ly;
    hw = *(uint32_t*)&hp;
    lw = *(uint32_t*)&lp;
}
__device__ __forceinline__ uint32_t saddr(const void* p) {
    return (uint32_t)__cvta_generic_to_shared(p);
}
__device__ __forceinline__ void cp16(uint32_t dst, const void* src) {
    asm volatile("cp.async.cg.shared.global [%0], [%1], 16;" :: "r"(dst), "l"(src));
}
#define CP_COMMIT() asm volatile("cp.async.commit_group;")
#define CP_WAIT0()  asm volatile("cp.async.wait_group 0;")
#define CP_WAIT1()  asm volatile("cp.async.wait_group 1;")

__device__ __forceinline__ void mma_bf16(float c[4],
                                         uint32_t a0, uint32_t a1, uint32_t a2, uint32_t a3,
                                         uint32_t b0, uint32_t b1) {
    asm volatile(
        "mma.sync.aligned.m16n8k16.row.col.f32.bf16.bf16.f32 "
        "{%0,%1,%2,%3}, {%4,%5,%6,%7}, {%8,%9}, {%0,%1,%2,%3};"
        : "+f"(c[0]), "+f"(c[1]), "+f"(c[2]), "+f"(c[3])
        : "r"(a0), "r"(a1), "r"(a2), "r"(a3), "r"(b0), "r"(b1));
}
__device__ __forceinline__ void mma_f16(float c[4],
                                        uint32_t a0, uint32_t a1, uint32_t a2, uint32_t a3,
                                        uint32_t b0, uint32_t b1) {
    asm volatile(
        "mma.sync.aligned.m16n8k16.row.col.f32.f16.f16.f32 "
        "{%0,%1,%2,%3}, {%4,%5,%6,%7}, {%8,%9}, {%0,%1,%2,%3};"
        : "+f"(c[0]), "+f"(c[1]), "+f"(c[2]), "+f"(c[3])
        : "r"(a0), "r"(a1), "r"(a2), "r"(a3), "r"(b0), "r"(b1));
}

// ---------------------------------------------------------------------------
// split kernel: fp32[n] -> bf16 hi[n], lo[n]   (n4 = n/4 float4s)
// ---------------------------------------------------------------------------
__global__ void split_kernel(const float* __restrict__ in,
                             __nv_bfloat16* __restrict__ oh,
                             __nv_bfloat16* __restrict__ ol, int n4)
{
    const int i = blockIdx.x * blockDim.x + threadIdx.x;
    if (i >= n4) return;
    const float4 v = ((const float4*)in)[i];
    uint32_t h01, l01, h23, l23;
    split2_bf16(v.x, v.y, h01, l01);
    split2_bf16(v.z, v.w, h23, l23);
    uint2 th = {h01, h23}, tl = {l01, l23};
    ((uint2*)oh)[i] = th;
    ((uint2*)ol)[i] = tl;
}

// ---------------------------------------------------------------------------
// Split-input bf16x3 GEMM (TRANS_B), cp.async 2-stage pipeline.
// C[m,n] = sum_k A[m,k]*B[n,k] (+bias).  Tiles 128x128x32, 8 warps 2x4.
// smem per stage: Ah[128][20],Al,Bh,Bl u32 (bf16 pairs) = 40960 B.
// ---------------------------------------------------------------------------
template<bool BIAS>
__global__ __launch_bounds__(256, 2)
void gemm_sp(const __nv_bfloat16* __restrict__ ah, const __nv_bfloat16* __restrict__ al,
             const __nv_bfloat16* __restrict__ bh, const __nv_bfloat16* __restrict__ bl,
             float* __restrict__ C, const float* __restrict__ bias,
             int M, int N, int K, int lda, int ldb, int ldc)
{
    extern __shared__ uint32_t sm[];
    const int tid  = threadIdx.x;
    const int warp = tid >> 5, lane = tid & 31;
    const int wm = (warp >> 2) * 64, wn = (warp & 3) * 32;
    const int m0 = blockIdx.y * 128, n0 = blockIdx.x * 128;
    const int ar = lane >> 2, ac = lane & 3;
    const int br = lane & 3,  bc = lane >> 2;

    float acc[4][4][4];
#pragma unroll
    for (int i = 0; i < 4; i++)
#pragma unroll
        for (int j = 0; j < 4; j++)
#pragma unroll
            for (int r = 0; r < 4; r++) acc[i][j][r] = 0.f;

    auto stage = [&](int s, int k0) {
        uint32_t* B0 = sm + s * 10240;
#pragma unroll
        for (int i = tid; i < 512; i += 256) {
            const int r = i >> 2, c = i & 3;
            cp16(saddr(B0        + r * 20 + c * 4), (const uint4*)(ah + (size_t)(m0 + r) * lda + k0) + c);
            cp16(saddr(B0 + 2560 + r * 20 + c * 4), (const uint4*)(al + (size_t)(m0 + r) * lda + k0) + c);
            cp16(saddr(B0 + 5120 + r * 20 + c * 4), (const uint4*)(bh + (size_t)(n0 + r) * ldb + k0) + c);
            cp16(saddr(B0 + 7680 + r * 20 + c * 4), (const uint4*)(bl + (size_t)(n0 + r) * ldb + k0) + c);
        }
    };

    const int T = K / 32;
    stage(0, 0);
    CP_COMMIT();

    for (int t = 0; t < T; t++) {
        if (t + 1 < T) {
            stage((t + 1) & 1, (t + 1) * 32);
            CP_COMMIT();
            CP_WAIT1();
        } else {
            CP_WAIT0();
        }
        __syncthreads();

        const uint32_t* Ah = sm + (t & 1) * 10240;
        const uint32_t* Al = Ah + 2560;
        const uint32_t* Bh = Ah + 5120;
        const uint32_t* Bl = Ah + 7680;

#pragma unroll
        for (int kc = 0; kc < 16; kc += 8) {
            uint32_t bfh[4][2], bfl[4][2];
#pragma unroll
            for (int nt = 0; nt < 4; nt++) {
                const int nb = (wn + nt * 8 + bc) * 20;
                bfh[nt][0] = Bh[nb + kc + br];
                bfh[nt][1] = Bh[nb + kc + br + 4];
                bfl[nt][0] = Bl[nb + kc + br];
                bfl[nt][1] = Bl[nb + kc + br + 4];
            }
#pragma unroll
            for (int mt = 0; mt < 4; mt++) {
                const int r0 = (wm + mt * 16 + ar) * 20;
                const int r1 = (wm + mt * 16 + ar + 8) * 20;
                uint32_t ah0 = Ah[r0 + kc + ac],     ah1 = Ah[r1 + kc + ac];
                uint32_t ah2 = Ah[r0 + kc + ac + 4], ah3 = Ah[r1 + kc + ac + 4];
                uint32_t al0 = Al[r0 + kc + ac],     al1 = Al[r1 + kc + ac];
                uint32_t al2 = Al[r0 + kc + ac + 4], al3 = Al[r1 + kc + ac + 4];
#pragma unroll
                for (int nt = 0; nt < 4; nt++) {
                    mma_bf16(acc[mt][nt], ah0, ah1, ah2, ah3, bfl[nt][0], bfl[nt][1]);
                    mma_bf16(acc[mt][nt], al0, al1, al2, al3, bfh[nt][0], bfh[nt][1]);
                    mma_bf16(acc[mt][nt], ah0, ah1, ah2, ah3, bfh[nt][0], bfh[nt][1]);
                }
            }
        }
        __syncthreads();
    }

    const int cr = lane >> 2, cc = (lane & 3) * 2;
#pragma unroll
    for (int mt = 0; mt < 4; mt++) {
#pragma unroll
        for (int nt = 0; nt < 4; nt++) {
            const int m = m0 + wm + mt * 16 + cr;
            const int n = n0 + wn + nt * 8 + cc;
            float2 v0, v1;
            v0.x = acc[mt][nt][0]; v0.y = acc[mt][nt][1];
            v1.x = acc[mt][nt][2]; v1.y = acc[mt][nt][3];
            if (BIAS) {
                const float b0 = bias[n], b1 = bias[n + 1];
                v0.x += b0; v0.y += b1;
                v1.x += b0; v1.y += b1;
            }
            *(float2*)(C + (size_t)m       * ldc + n) = v0;
            *(float2*)(C + (size_t)(m + 8) * ldc + n) = v1;
        }
    }
}

// ---------------------------------------------------------------------------
// norm_rope_split: RMSNorm+RoPE on q/k -> split bf16; v -> fp16 transposed.
// grid = 3*NH*LQ blocks, 128 threads.
// ---------------------------------------------------------------------------
__global__ void norm_rope_split(const float* __restrict__ pe,
                                const float* __restrict__ q_scale,
                                const float* __restrict__ k_scale)
{
    const int idx = blockIdx.x;
    const int l   = idx & (LQ - 1);
    const int h   = (idx >> 11) & (NH - 1);
    const int qk  = idx >> 15;                  // 0=q, 1=k, 2=v
    const int d   = threadIdx.x;
    const int lane = d & 31, warp = d >> 5;

    const float* row = g_qkv + (size_t)l * QKV_N + qk * DIM + h * HD;
    const float t = row[d];

    if (qk == 2) {
        g_vt[(size_t)(h * HD + d) * LQ + l] = __float2half_rn(t);
        return;
    }

    float ss = t * t;
#pragma unroll
    for (int o = 16; o > 0; o >>= 1) ss += __shfl_xor_sync(0xFFFFFFFFu, ss, o);
    __shared__ float red[4];
    if (lane == 0) red[warp] = ss;
    __syncthreads();
    const float tot = red[0] + red[1] + red[2] + red[3];
    const float rrms = rsqrtf(tot * (1.0f / HD) + 1e-6f);

    const float* scale = qk ? k_scale : q_scale;
    const float tn = t * rrms * scale[d];

    const float other = __shfl_xor_sync(0xFFFFFFFFu, tn, 1);
    const int j = d >> 1, s = d & 1;
    const float* pp = pe + ((size_t)l * (HD / 2) + j) * 4 + s * 2;
    const float te = (s == 0) ? tn : other;
    const float to = (s == 0) ? other : tn;
    const float roped = pp[0] * te + pp[1] * to;

    __shared__ float buf[HD];
    buf[d] = roped;
    __syncthreads();
    if (d < 64) {
        uint32_t hw, lw;
        split2_bf16(buf[2 * d], buf[2 * d + 1], hw, lw);
        const size_t o32 = ((size_t)l * DIM + h * HD) / 2 + d;
        if (qk == 0) { ((uint32_t*)g_qh)[o32] = hw; ((uint32_t*)g_ql)[o32] = lw; }
        else         { ((uint32_t*)g_kh)[o32] = hw; ((uint32_t*)g_kl)[o32] = lw; }
    }
}

// ---------------------------------------------------------------------------
// Flash attention: grid (16 q-blocks, 16 heads), 256 threads (8 warps 2x4).
// Scores bf16x3, online softmax, P@V fp16 single-MMA.
// smem (u32): Qh[128*68] Ql Kh(->Ps fp16) Kl Vs(fp16) + redm/redl.
// ---------------------------------------------------------------------------
__global__ __launch_bounds__(256, 1)
void flash_kernel()
{
    extern __shared__ uint32_t sm[];
    uint32_t* Qh = sm;
    uint32_t* Ql = sm + 8704;
    uint32_t* Kh = sm + 17408;   // also Ps (fp16 pairs)
    uint32_t* Kl = sm + 26112;
    uint32_t* Vs = sm + 34816;   // fp16 pairs [d][68]
    float* redm = (float*)(sm + 43520);   // [2][4][64]
    float* redl = (float*)(sm + 44032);

    const int tid  = threadIdx.x;
    const int warp = tid >> 5, lane = tid & 31;
    const int wm = (warp >> 2) * 64, wn = (warp & 3) * 32;
    const int wr = warp >> 2, wc = warp & 3;
    const int qb = blockIdx.x, h = blockIdx.y;
    const int ar = lane >> 2, ac = lane & 3;
    const int br = lane & 3,  bc = lane >> 2;
    const int l3 = lane & 3;

    // stage Q block (rows qb*128..+127)
#pragma unroll
    for (int i = tid; i < 2048; i += 256) {
        const int r = i >> 4, c = i & 15;
        const size_t off = ((size_t)(qb * 128 + r) * DIM + h * HD) / 2;
        cp16(saddr(Qh + r * 68 + c * 4), (const uint4*)((const uint32_t*)g_qh + off) + c);
        cp16(saddr(Ql + r * 68 + c * 4), (const uint4*)((const uint32_t*)g_ql + off) + c);
    }
    CP_COMMIT();

    float o[4][4][4];
    float s[4][4][4];
    float mst[4][2], lst[4][2], corr[4][2];
#pragma unroll
    for (int i = 0; i < 4; i++) {
#pragma unroll
        for (int j = 0; j < 4; j++)
#pragma unroll
            for (int r = 0; r < 4; r++) o[i][j][r] = 0.f;
        mst[i][0] = -1e30f; mst[i][1] = -1e30f;
        lst[i][0] = 0.f;    lst[i][1] = 0.f;
    }

    for (int kb = 0; kb < 16; kb++) {
        if (kb) __syncthreads();   // protect Ps/Vs from previous PV reads

        // stage K and V blocks
#pragma unroll
        for (int i = tid; i < 2048; i += 256) {
            const int r = i >> 4, c = i & 15;
            const size_t off = ((size_t)(kb * 128 + r) * DIM + h * HD) / 2;
            cp16(saddr(Kh + r * 68 + c * 4), (const uint4*)((const uint32_t*)g_kh + off) + c);
            cp16(saddr(Kl + r * 68 + c * 4), (const uint4*)((const uint32_t*)g_kl + off) + c);
        }
#pragma unroll
        for (int i = tid; i < 2048; i += 256) {
            const int r = i >> 4, c = i & 15;
            const size_t off = ((size_t)(h * HD + r) * LQ + kb * 128) / 2;
            cp16(saddr(Vs + r * 68 + c * 4), (const uint4*)((const uint32_t*)g_vt + off) + c);
        }
        CP_COMMIT();
        CP_WAIT0();
        __syncthreads();

        // ---- S = Q @ K^T (bf16x3) ----
#pragma unroll
        for (int i = 0; i < 4; i++)
#pragma unroll
            for (int j = 0; j < 4; j++)
#pragma unroll
                for (int r = 0; r < 4; r++) s[i][j][r] = 0.f;

#pragma unroll
        for (int kc = 0; kc < 64; kc += 8) {
            uint32_t bfh[4][2], bfl[4][2];
#pragma unroll
            for (int nt = 0; nt < 4; nt++) {
                const int nb = (wn + nt * 8 + bc) * 68;
                bfh[nt][0] = Kh[nb + kc + br];
                bfh[nt][1] = Kh[nb + kc + br + 4];
                bfl[nt][0] = Kl[nb + kc + br];
                bfl[nt][1] = Kl[nb + kc + br + 4];
            }
#pragma unroll
            for (int mt = 0; mt < 4; mt++) {
                const int r0 = (wm + mt * 16 + ar) * 68;
                const int r1 = r0 + 8 * 68;
                uint32_t ah0 = Qh[r0 + kc + ac],     ah1 = Qh[r1 + kc + ac];
                uint32_t ah2 = Qh[r0 + kc + ac + 4], ah3 = Qh[r1 + kc + ac + 4];
                uint32_t al0 = Ql[r0 + kc + ac],     al1 = Ql[r1 + kc + ac];
                uint32_t al2 = Ql[r0 + kc + ac + 4], al3 = Ql[r1 + kc + ac + 4];
#pragma unroll
                for (int nt = 0; nt < 4; nt++) {
                    mma_bf16(s[mt][nt], ah0, ah1, ah2, ah3, bfl[nt][0], bfl[nt][1]);
                    mma_bf16(s[mt][nt], al0, al1, al2, al3, bfh[nt][0], bfh[nt][1]);
                    mma_bf16(s[mt][nt], ah0, ah1, ah2, ah3, bfh[nt][0], bfh[nt][1]);
                }
            }
        }

        // ---- row max (warp-local then cross-warp) ----
#pragma unroll
        for (int mt = 0; mt < 4; mt++) {
#pragma unroll
            for (int hf = 0; hf < 2; hf++) {
                float mx = -1e30f;
#pragma unroll
                for (int nt = 0; nt < 4; nt++) {
                    mx = fmaxf(mx, s[mt][nt][2 * hf]);
                    mx = fmaxf(mx, s[mt][nt][2 * hf + 1]);
                }
                mx = fmaxf(mx, __shfl_xor_sync(0xFFFFFFFFu, mx, 1));
                mx = fmaxf(mx, __shfl_xor_sync(0xFFFFFFFFu, mx, 2));
                if (l3 == 0) redm[wr * 256 + wc * 64 + mt * 16 + ar + 8 * hf] = mx;
            }
        }
        __syncthreads();

        float psum[4][2];
#pragma unroll
        for (int mt = 0; mt < 4; mt++) {
#pragma unroll
            for (int hf = 0; hf < 2; hf++) {
                const int r = mt * 16 + ar + 8 * hf;
                float gm = redm[wr * 256 + r];
                gm = fmaxf(gm, redm[wr * 256 + 64 + r]);
                gm = fmaxf(gm, redm[wr * 256 + 128 + r]);
                gm = fmaxf(gm, redm[wr * 256 + 192 + r]);
                const float mnew = fmaxf(mst[mt][hf], gm);
                corr[mt][hf] = __expf((mst[mt][hf] - mnew) * SCALE);
                mst[mt][hf] = mnew;
                psum[mt][hf] = 0.f;
            }
        }

        // rescale O, exponentiate S -> P, partial sums, write P(fp16) to Ps(=Kh)
#pragma unroll
        for (int mt = 0; mt < 4; mt++) {
#pragma unroll
            for (int nt = 0; nt < 4; nt++) {
#pragma unroll
                for (int hf = 0; hf < 2; hf++) {
                    o[mt][nt][2 * hf]     *= corr[mt][hf];
                    o[mt][nt][2 * hf + 1] *= corr[mt][hf];
                    const float p0 = __expf((s[mt][nt][2 * hf]     - mst[mt][hf]) * SCALE);
                    const float p1 = __expf((s[mt][nt][2 * hf + 1] - mst[mt][hf]) * SCALE);
                    psum[mt][hf] += p0 + p1;
                    const __half2 hp = __floats2half2_rn(p0, p1);
                    const int q  = wm + mt * 16 + ar + 8 * hf;
                    const int kp = (wn >> 1) + nt * 4 + l3;
                    Kh[q * 68 + kp] = *(const uint32_t*)&hp;
                }
            }
        }
#pragma unroll
        for (int mt = 0; mt < 4; mt++) {
#pragma unroll
            for (int hf = 0; hf < 2; hf++) {
                float sv = psum[mt][hf];
                sv += __shfl_xor_sync(0xFFFFFFFFu, sv, 1);
                sv += __shfl_xor_sync(0xFFFFFFFFu, sv, 2);
                if (l3 == 0) redl[wr * 256 + wc * 64 + mt * 16 + ar + 8 * hf] = sv;
            }
        }
        __syncthreads();   // redl ready + all P writes visible

#pragma unroll
        for (int mt = 0; mt < 4; mt++) {
#pragma unroll
            for (int hf = 0; hf < 2; hf++) {
                const int r = mt * 16 + ar + 8 * hf;
                const float gs = redl[wr * 256 + r] + redl[wr * 256 + 64 + r]
                               + redl[wr * 256 + 128 + r] + redl[wr * 256 + 192 + r];
                lst[mt][hf] = lst[mt][hf] * corr[mt][hf] + gs;
            }
        }

        // ---- O += P @ V (fp16 single MMA) ----
#pragma unroll
        for (int kc = 0; kc < 64; kc += 8) {
            uint32_t bf[4][2];
#pragma unroll
            for (int nt = 0; nt < 4; nt++) {
                const int nb = (wn + nt * 8 + bc) * 68;
                bf[nt][0] = Vs[nb + kc + br];
                bf[nt][1] = Vs[nb + kc + br + 4];
            }
#pragma unroll
            for (int mt = 0; mt < 4; mt++) {
                const int r0 = (wm + mt * 16 + ar) * 68;
                const int r1 = r0 + 8 * 68;
                uint32_t a0 = Kh[r0 + kc + ac],     a1 = Kh[r1 + kc + ac];
                uint32_t a2 = Kh[r0 + kc + ac + 4], a3 = Kh[r1 + kc + ac + 4];
#pragma unroll
                for (int nt = 0; nt < 4; nt++)
                    mma_f16(o[mt][nt], a0, a1, a2, a3, bf[nt][0], bf[nt][1]);
            }
        }
    }

    // ---- epilogue: O/l -> split bf16 -> g_ah/g_al at [q][h*128+d] ----
#pragma unroll
    for (int mt = 0; mt < 4; mt++) {
#pragma unroll
        for (int hf = 0; hf < 2; hf++) {
            const float inv = 1.0f / lst[mt][hf];
            const int q = qb * 128 + wm + mt * 16 + ar + 8 * hf;
#pragma unroll
            for (int nt = 0; nt < 4; nt++) {
                const float o0 = o[mt][nt][2 * hf] * inv;
                const float o1 = o[mt][nt][2 * hf + 1] * inv;
                uint32_t hw, lw;
                split2_bf16(o0, o1, hw, lw);
                const size_t idx = ((size_t)q * DIM + h * HD + wn + nt * 8) / 2 + l3;
                ((uint32_t*)g_ah)[idx] = hw;
                ((uint32_t*)g_al)[idx] = lw;
            }
        }
    }
}

// ---------------------------------------------------------------------------
// Launch
// ---------------------------------------------------------------------------
extern "C" void kernel_launch(void* const* d_in, const int* in_sizes, int n_in,
                              void* d_out, int out_size)
{
    const float* x       = (const float*)d_in[0];
    const float* pe      = (const float*)d_in[1];
    const float* qkv_w   = (const float*)d_in[2];
    const float* q_scale = (const float*)d_in[3];
    const float* k_scale = (const float*)d_in[4];
    const float* proj_w  = (const float*)d_in[5];
    const float* proj_b  = (const float*)d_in[6];
    float* out = (float*)d_out;

    float* qkv;
    __nv_bfloat16 *xh, *xl, *wh, *wl, *pwh, *pwl, *ah, *al;
    cudaGetSymbolAddress((void**)&qkv, g_qkv);
    cudaGetSymbolAddress((void**)&xh,  g_xh);
    cudaGetSymbolAddress((void**)&xl,  g_xl);
    cudaGetSymbolAddress((void**)&wh,  g_wh);
    cudaGetSymbolAddress((void**)&wl,  g_wl);
    cudaGetSymbolAddress((void**)&pwh, g_pwh);
    cudaGetSymbolAddress((void**)&pwl, g_pwl);
    cudaGetSymbolAddress((void**)&ah,  g_ah);
    cudaGetSymbolAddress((void**)&al,  g_al);

    const int GEMM_SMEM  = 81920;
    const int FLASH_SMEM = 178176;
    cudaFuncSetAttribute(gemm_sp<false>, cudaFuncAttributeMaxDynamicSharedMemorySize, GEMM_SMEM);
    cudaFuncSetAttribute(gemm_sp<true>,  cudaFuncAttributeMaxDynamicSharedMemorySize, GEMM_SMEM);
    cudaFuncSetAttribute(flash_kernel,   cudaFuncAttributeMaxDynamicSharedMemorySize, FLASH_SMEM);

    // 0) pre-split inputs
    split_kernel<<<(LQ * DIM / 4 + 255) / 256, 256>>>(x, xh, xl, LQ * DIM / 4);
    split_kernel<<<(QKV_N * DIM / 4 + 255) / 256, 256>>>(qkv_w, wh, wl, QKV_N * DIM / 4);
    split_kernel<<<(DIM * DIM / 4 + 255) / 256, 256>>>(proj_w, pwh, pwl, DIM * DIM / 4);

    // 1) qkv = x @ qkv_w^T
    {
        dim3 grid(QKV_N / 128, LQ / 128);
        gemm_sp<false><<<grid, 256, GEMM_SMEM>>>(xh, xl, wh, wl, qkv, nullptr,
                                                 LQ, QKV_N, DIM, DIM, DIM, QKV_N);
    }

    // 2) RMSNorm + RoPE + splits (q,k) and V -> fp16 transposed
    norm_rope_split<<<3 * NH * LQ, 128>>>(pe, q_scale, k_scale);

    // 3) flash attention -> g_ah/g_al
    {
        dim3 grid(LQ / 128, NH);
        flash_kernel<<<grid, 256, FLASH_SMEM>>>();
    }

    // 4) out = att @ proj_w^T + proj_b
    {
        dim3 grid(DIM / 128, LQ / 128);
        gemm_sp<true><<<grid, 256, GEMM_SMEM>>>(ah, al, pwh, pwl, out, proj_b,
                                                LQ, DIM, DIM, DIM, DIM, DIM);
    }
}

// round 11
// speedup vs baseline: 2.8513x; 1.0310x over previous
#include <cuda_runtime.h>
#include <cuda_bf16.h>
#include <cuda_fp16.h>
#include <cstdint>

// ---------------------------------------------------------------------------
#define LQ    2048
#define DIM   2048
#define NH    16
#define HD    128
#define QKV_N 6144
#define SCALE 0.08838834764831845f   // 1/sqrt(128)

// ---------------------------------------------------------------------------
// Scratch (__device__ globals; allocation-free rule)
// ---------------------------------------------------------------------------
__device__ float g_qkv[(size_t)LQ * QKV_N];                         // fp32 qkv
__device__ __nv_bfloat16 g_xh[(size_t)LQ * DIM],  g_xl[(size_t)LQ * DIM];
__device__ __nv_bfloat16 g_wh[(size_t)QKV_N * DIM], g_wl[(size_t)QKV_N * DIM];
__device__ __nv_bfloat16 g_pwh[(size_t)DIM * DIM],  g_pwl[(size_t)DIM * DIM];
__device__ __nv_bfloat16 g_qh[(size_t)LQ * DIM],  g_ql[(size_t)LQ * DIM];
__device__ __nv_bfloat16 g_kh[(size_t)LQ * DIM],  g_kl[(size_t)LQ * DIM];
__device__ __half        g_vt[(size_t)DIM * LQ];                     // V^T: [h*128+d][L] fp16
__device__ __nv_bfloat16 g_ah[(size_t)LQ * DIM],  g_al[(size_t)LQ * DIM];

// ---------------------------------------------------------------------------
// helpers
// ---------------------------------------------------------------------------
__device__ __forceinline__ void split_bf16(float f, __nv_bfloat16& h, __nv_bfloat16& l) {
    h = __float2bfloat16_rn(f);
    l = __float2bfloat16_rn(f - __bfloat162float(h));
}
__device__ __forceinline__ void split2_bf16(float x, float y, uint32_t& hw, uint32_t& lw) {
    __nv_bfloat16 hx, lx, hy, ly;
    split_bf16(x, hx, lx);
    split_bf16(y, hy, ly);
    __nv_bfloat162 hp, lp;
    hp.x = hx; hp.y = hy;
    lp.x = lx; lp.y = ly;
    hw = *(uint32_t*)&hp;
    lw = *(uint32_t*)&lp;
}
__device__ __forceinline__ uint32_t saddr(const void* p) {
    return (uint32_t)__cvta_generic_to_shared(p);
}
__device__ __forceinline__ void cp16(uint32_t dst, const void* src) {
    asm volatile("cp.async.cg.shared.global [%0], [%1], 16;" :: "r"(dst), "l"(src));
}
#define CP_COMMIT() asm volatile("cp.async.commit_group;")
#define CP_WAIT0()  asm volatile("cp.async.wait_group 0;")
#define CP_WAIT1()  asm volatile("cp.async.wait_group 1;")

// ldmatrix.x4: 4 8x8 b16 matrices; per-lane row addresses (lane i -> matrix i>>3, row i&7)
__device__ __forceinline__ void ldsm4(uint32_t& r0, uint32_t& r1, uint32_t& r2, uint32_t& r3,
                                      uint32_t addr) {
    asm volatile("ldmatrix.sync.aligned.m8n8.x4.shared.b16 {%0,%1,%2,%3}, [%4];"
                 : "=r"(r0), "=r"(r1), "=r"(r2), "=r"(r3) : "r"(addr));
}

__device__ __forceinline__ void mma_bf16(float c[4],
                                         uint32_t a0, uint32_t a1, uint32_t a2, uint32_t a3,
                                         uint32_t b0, uint32_t b1) {
    asm volatile(
        "mma.sync.aligned.m16n8k16.row.col.f32.bf16.bf16.f32 "
        "{%0,%1,%2,%3}, {%4,%5,%6,%7}, {%8,%9}, {%0,%1,%2,%3};"
        : "+f"(c[0]), "+f"(c[1]), "+f"(c[2]), "+f"(c[3])
        : "r"(a0), "r"(a1), "r"(a2), "r"(a3), "r"(b0), "r"(b1));
}
__device__ __forceinline__ void mma_f16(float c[4],
                                        uint32_t a0, uint32_t a1, uint32_t a2, uint32_t a3,
                                        uint32_t b0, uint32_t b1) {
    asm volatile(
        "mma.sync.aligned.m16n8k16.row.col.f32.f16.f16.f32 "
        "{%0,%1,%2,%3}, {%4,%5,%6,%7}, {%8,%9}, {%0,%1,%2,%3};"
        : "+f"(c[0]), "+f"(c[1]), "+f"(c[2]), "+f"(c[3])
        : "r"(a0), "r"(a1), "r"(a2), "r"(a3), "r"(b0), "r"(b1));
}

// ---------------------------------------------------------------------------
// split kernel: fp32[n] -> bf16 hi[n], lo[n]   (n4 = n/4 float4s)
// ---------------------------------------------------------------------------
__global__ void split_kernel(const float* __restrict__ in,
                             __nv_bfloat16* __restrict__ oh,
                             __nv_bfloat16* __restrict__ ol, int n4)
{
    const int i = blockIdx.x * blockDim.x + threadIdx.x;
    if (i >= n4) return;
    const float4 v = ((const float4*)in)[i];
    uint32_t h01, l01, h23, l23;
    split2_bf16(v.x, v.y, h01, l01);
    split2_bf16(v.z, v.w, h23, l23);
    uint2 th = {h01, h23}, tl = {l01, l23};
    ((uint2*)oh)[i] = th;
    ((uint2*)ol)[i] = tl;
}

// ---------------------------------------------------------------------------
// Split-input bf16x3 GEMM (A@B^T), cp.async 2-stage pipeline, ldmatrix frags.
// C[m,n] = sum_k A[m,k]*B[n,k] (+bias).  Tiles 128x128x32, 8 warps 2x4.
// Stage layout (u32): Ah[128][20] | Al | Bh | Bl  = 10240 u32 = 40960 B.
// ---------------------------------------------------------------------------
template<bool BIAS>
__global__ __launch_bounds__(256, 2)
void gemm_sp(const __nv_bfloat16* __restrict__ ah, const __nv_bfloat16* __restrict__ al,
             const __nv_bfloat16* __restrict__ bh, const __nv_bfloat16* __restrict__ bl,
             float* __restrict__ C, const float* __restrict__ bias,
             int M, int N, int K, int lda, int ldb, int ldc)
{
    extern __shared__ uint32_t sm[];
    const uint32_t smb = saddr(sm);
    const int tid  = threadIdx.x;
    const int warp = tid >> 5, lane = tid & 31;
    const int wm = (warp >> 2) * 64, wn = (warp & 3) * 32;
    const int m0 = blockIdx.y * 128, n0 = blockIdx.x * 128;

    // ldmatrix per-lane row/col constants
    const int arow = (lane & 7) + ((lane >> 3) & 1) * 8;   // A: matrix pairs over m
    const int akp  = (lane >> 4) * 4;                      // A: kpair group
    const int brow = (lane & 7) + (lane >> 4) * 8;         // B: matrix pairs over n
    const int bkp  = ((lane >> 3) & 1) * 4;                // B: kpair group

    float acc[4][4][4];
#pragma unroll
    for (int i = 0; i < 4; i++)
#pragma unroll
        for (int j = 0; j < 4; j++)
#pragma unroll
            for (int r = 0; r < 4; r++) acc[i][j][r] = 0.f;

    auto stage = [&](int s, int k0) {
        uint32_t* B0 = sm + s * 10240;
#pragma unroll
        for (int i = tid; i < 512; i += 256) {
            const int r = i >> 2, c = i & 3;
            cp16(saddr(B0        + r * 20 + c * 4), (const uint4*)(ah + (size_t)(m0 + r) * lda + k0) + c);
            cp16(saddr(B0 + 2560 + r * 20 + c * 4), (const uint4*)(al + (size_t)(m0 + r) * lda + k0) + c);
            cp16(saddr(B0 + 5120 + r * 20 + c * 4), (const uint4*)(bh + (size_t)(n0 + r) * ldb + k0) + c);
            cp16(saddr(B0 + 7680 + r * 20 + c * 4), (const uint4*)(bl + (size_t)(n0 + r) * ldb + k0) + c);
        }
    };

    const int T = K / 32;
    stage(0, 0);
    CP_COMMIT();

    for (int t = 0; t < T; t++) {
        if (t + 1 < T) {
            stage((t + 1) & 1, (t + 1) * 32);
            CP_COMMIT();
            CP_WAIT1();
        } else {
            CP_WAIT0();
        }
        __syncthreads();

        const uint32_t stg = smb + (t & 1) * 40960;

#pragma unroll
        for (int kc = 0; kc < 16; kc += 8) {
            uint32_t bfh[4][2], bfl[4][2];
#pragma unroll
            for (int g = 0; g < 2; g++) {
                const uint32_t bi = (uint32_t)((wn + g * 16 + brow) * 20 + kc + bkp) * 4;
                ldsm4(bfh[2*g][0], bfh[2*g][1], bfh[2*g+1][0], bfh[2*g+1][1], stg + 20480 + bi);
                ldsm4(bfl[2*g][0], bfl[2*g][1], bfl[2*g+1][0], bfl[2*g+1][1], stg + 30720 + bi);
            }
#pragma unroll
            for (int mt = 0; mt < 4; mt++) {
                const uint32_t ai = (uint32_t)((wm + mt * 16 + arow) * 20 + kc + akp) * 4;
                uint32_t ah0, ah1, ah2, ah3, al0, al1, al2, al3;
                ldsm4(ah0, ah1, ah2, ah3, stg + ai);
                ldsm4(al0, al1, al2, al3, stg + 10240 + ai);
#pragma unroll
                for (int nt = 0; nt < 4; nt++) {
                    mma_bf16(acc[mt][nt], ah0, ah1, ah2, ah3, bfl[nt][0], bfl[nt][1]);
                    mma_bf16(acc[mt][nt], al0, al1, al2, al3, bfh[nt][0], bfh[nt][1]);
                    mma_bf16(acc[mt][nt], ah0, ah1, ah2, ah3, bfh[nt][0], bfh[nt][1]);
                }
            }
        }
        __syncthreads();
    }

    const int cr = lane >> 2, cc = (lane & 3) * 2;
#pragma unroll
    for (int mt = 0; mt < 4; mt++) {
#pragma unroll
        for (int nt = 0; nt < 4; nt++) {
            const int m = m0 + wm + mt * 16 + cr;
            const int n = n0 + wn + nt * 8 + cc;
            float2 v0, v1;
            v0.x = acc[mt][nt][0]; v0.y = acc[mt][nt][1];
            v1.x = acc[mt][nt][2]; v1.y = acc[mt][nt][3];
            if (BIAS) {
                const float b0 = bias[n], b1 = bias[n + 1];
                v0.x += b0; v0.y += b1;
                v1.x += b0; v1.y += b1;
            }
            *(float2*)(C + (size_t)m       * ldc + n) = v0;
            *(float2*)(C + (size_t)(m + 8) * ldc + n) = v1;
        }
    }
}

// ---------------------------------------------------------------------------
// norm_rope_split: RMSNorm+RoPE on q/k -> split bf16; v -> fp16 transposed.
// grid = 3*NH*LQ blocks, 128 threads.
// ---------------------------------------------------------------------------
__global__ void norm_rope_split(const float* __restrict__ pe,
                                const float* __restrict__ q_scale,
                                const float* __restrict__ k_scale)
{
    const int idx = blockIdx.x;
    const int l   = idx & (LQ - 1);
    const int h   = (idx >> 11) & (NH - 1);
    const int qk  = idx >> 15;                  // 0=q, 1=k, 2=v
    const int d   = threadIdx.x;
    const int lane = d & 31, warp = d >> 5;

    const float* row = g_qkv + (size_t)l * QKV_N + qk * DIM + h * HD;
    const float t = row[d];

    if (qk == 2) {
        g_vt[(size_t)(h * HD + d) * LQ + l] = __float2half_rn(t);
        return;
    }

    float ss = t * t;
#pragma unroll
    for (int o = 16; o > 0; o >>= 1) ss += __shfl_xor_sync(0xFFFFFFFFu, ss, o);
    __shared__ float red[4];
    if (lane == 0) red[warp] = ss;
    __syncthreads();
    const float tot = red[0] + red[1] + red[2] + red[3];
    const float rrms = rsqrtf(tot * (1.0f / HD) + 1e-6f);

    const float* scale = qk ? k_scale : q_scale;
    const float tn = t * rrms * scale[d];

    const float other = __shfl_xor_sync(0xFFFFFFFFu, tn, 1);
    const int j = d >> 1, s = d & 1;
    const float* pp = pe + ((size_t)l * (HD / 2) + j) * 4 + s * 2;
    const float te = (s == 0) ? tn : other;
    const float to = (s == 0) ? other : tn;
    const float roped = pp[0] * te + pp[1] * to;

    __shared__ float buf[HD];
    buf[d] = roped;
    __syncthreads();
    if (d < 64) {
        uint32_t hw, lw;
        split2_bf16(buf[2 * d], buf[2 * d + 1], hw, lw);
        const size_t o32 = ((size_t)l * DIM + h * HD) / 2 + d;
        if (qk == 0) { ((uint32_t*)g_qh)[o32] = hw; ((uint32_t*)g_ql)[o32] = lw; }
        else         { ((uint32_t*)g_kh)[o32] = hw; ((uint32_t*)g_kl)[o32] = lw; }
    }
}

// ---------------------------------------------------------------------------
// Flash attention: grid (16 q-blocks, 16 heads), 256 threads (8 warps 2x4).
// Scores bf16x3 (ldmatrix frags), online softmax, P@V fp16 single-MMA.
// smem (u32): Qh[128*68] Ql Kh(->Ps fp16) Kl Vs(fp16) + redm/redl.
// Stride 68 == 4 mod 32 -> ldmatrix 8-row phases conflict-free.
// ---------------------------------------------------------------------------
__global__ __launch_bounds__(256, 1)
void flash_kernel()
{
    extern __shared__ uint32_t sm[];
    const uint32_t smb = saddr(sm);
    uint32_t* Qh = sm;
    uint32_t* Ql = sm + 8704;
    uint32_t* Kh = sm + 17408;   // also Ps (fp16 pairs)
    uint32_t* Kl = sm + 26112;
    uint32_t* Vs = sm + 34816;   // fp16 pairs [d][68]
    float* redm = (float*)(sm + 43520);   // [2][4][64]
    float* redl = (float*)(sm + 44032);

    const int tid  = threadIdx.x;
    const int warp = tid >> 5, lane = tid & 31;
    const int wm = (warp >> 2) * 64, wn = (warp & 3) * 32;
    const int wr = warp >> 2, wc = warp & 3;
    const int qb = blockIdx.x, h = blockIdx.y;
    const int ar = lane >> 2;
    const int l3 = lane & 3;

    const int arow = (lane & 7) + ((lane >> 3) & 1) * 8;
    const int akp  = (lane >> 4) * 4;
    const int brow = (lane & 7) + (lane >> 4) * 8;
    const int bkp  = ((lane >> 3) & 1) * 4;

    // stage Q block (rows qb*128..+127)
#pragma unroll
    for (int i = tid; i < 2048; i += 256) {
        const int r = i >> 4, c = i & 15;
        const size_t off = ((size_t)(qb * 128 + r) * DIM + h * HD) / 2;
        cp16(saddr(Qh + r * 68 + c * 4), (const uint4*)((const uint32_t*)g_qh + off) + c);
        cp16(saddr(Ql + r * 68 + c * 4), (const uint4*)((const uint32_t*)g_ql + off) + c);
    }
    CP_COMMIT();

    float o[4][4][4];
    float s[4][4][4];
    float mst[4][2], lst[4][2], corr[4][2];
#pragma unroll
    for (int i = 0; i < 4; i++) {
#pragma unroll
        for (int j = 0; j < 4; j++)
#pragma unroll
            for (int r = 0; r < 4; r++) o[i][j][r] = 0.f;
        mst[i][0] = -1e30f; mst[i][1] = -1e30f;
        lst[i][0] = 0.f;    lst[i][1] = 0.f;
    }

    for (int kb = 0; kb < 16; kb++) {
        if (kb) __syncthreads();   // protect Ps/Vs from previous PV reads

        // stage K and V blocks
#pragma unroll
        for (int i = tid; i < 2048; i += 256) {
            const int r = i >> 4, c = i & 15;
            const size_t off = ((size_t)(kb * 128 + r) * DIM + h * HD) / 2;
            cp16(saddr(Kh + r * 68 + c * 4), (const uint4*)((const uint32_t*)g_kh + off) + c);
            cp16(saddr(Kl + r * 68 + c * 4), (const uint4*)((const uint32_t*)g_kl + off) + c);
        }
#pragma unroll
        for (int i = tid; i < 2048; i += 256) {
            const int r = i >> 4, c = i & 15;
            const size_t off = ((size_t)(h * HD + r) * LQ + kb * 128) / 2;
            cp16(saddr(Vs + r * 68 + c * 4), (const uint4*)((const uint32_t*)g_vt + off) + c);
        }
        CP_COMMIT();
        CP_WAIT0();
        __syncthreads();

        // ---- S = Q @ K^T (bf16x3, ldmatrix frags) ----
#pragma unroll
        for (int i = 0; i < 4; i++)
#pragma unroll
            for (int j = 0; j < 4; j++)
#pragma unroll
                for (int r = 0; r < 4; r++) s[i][j][r] = 0.f;

#pragma unroll
        for (int kc = 0; kc < 64; kc += 8) {
            uint32_t bfh[4][2], bfl[4][2];
#pragma unroll
            for (int g = 0; g < 2; g++) {
                const uint32_t bi = (uint32_t)((wn + g * 16 + brow) * 68 + kc + bkp) * 4;
                ldsm4(bfh[2*g][0], bfh[2*g][1], bfh[2*g+1][0], bfh[2*g+1][1], smb + 69632 + bi);
                ldsm4(bfl[2*g][0], bfl[2*g][1], bfl[2*g+1][0], bfl[2*g+1][1], smb + 104448 + bi);
            }
#pragma unroll
            for (int mt = 0; mt < 4; mt++) {
                const uint32_t ai = (uint32_t)((wm + mt * 16 + arow) * 68 + kc + akp) * 4;
                uint32_t qh0, qh1, qh2, qh3, ql0, ql1, ql2, ql3;
                ldsm4(qh0, qh1, qh2, qh3, smb + ai);
                ldsm4(ql0, ql1, ql2, ql3, smb + 34816 + ai);
#pragma unroll
                for (int nt = 0; nt < 4; nt++) {
                    mma_bf16(s[mt][nt], qh0, qh1, qh2, qh3, bfl[nt][0], bfl[nt][1]);
                    mma_bf16(s[mt][nt], ql0, ql1, ql2, ql3, bfh[nt][0], bfh[nt][1]);
                    mma_bf16(s[mt][nt], qh0, qh1, qh2, qh3, bfh[nt][0], bfh[nt][1]);
                }
            }
        }

        // ---- row max (warp-local then cross-warp) ----
#pragma unroll
        for (int mt = 0; mt < 4; mt++) {
#pragma unroll
            for (int hf = 0; hf < 2; hf++) {
                float mx = -1e30f;
#pragma unroll
                for (int nt = 0; nt < 4; nt++) {
                    mx = fmaxf(mx, s[mt][nt][2 * hf]);
                    mx = fmaxf(mx, s[mt][nt][2 * hf + 1]);
                }
                mx = fmaxf(mx, __shfl_xor_sync(0xFFFFFFFFu, mx, 1));
                mx = fmaxf(mx, __shfl_xor_sync(0xFFFFFFFFu, mx, 2));
                if (l3 == 0) redm[wr * 256 + wc * 64 + mt * 16 + ar + 8 * hf] = mx;
            }
        }
        __syncthreads();

        float psum[4][2];
#pragma unroll
        for (int mt = 0; mt < 4; mt++) {
#pragma unroll
            for (int hf = 0; hf < 2; hf++) {
                const int r = mt * 16 + ar + 8 * hf;
                float gm = redm[wr * 256 + r];
                gm = fmaxf(gm, redm[wr * 256 + 64 + r]);
                gm = fmaxf(gm, redm[wr * 256 + 128 + r]);
                gm = fmaxf(gm, redm[wr * 256 + 192 + r]);
                const float mnew = fmaxf(mst[mt][hf], gm);
                corr[mt][hf] = __expf((mst[mt][hf] - mnew) * SCALE);
                mst[mt][hf] = mnew;
                psum[mt][hf] = 0.f;
            }
        }

        // rescale O, exponentiate S -> P, partial sums, write P(fp16) to Ps(=Kh)
#pragma unroll
        for (int mt = 0; mt < 4; mt++) {
#pragma unroll
            for (int nt = 0; nt < 4; nt++) {
#pragma unroll
                for (int hf = 0; hf < 2; hf++) {
                    o[mt][nt][2 * hf]     *= corr[mt][hf];
                    o[mt][nt][2 * hf + 1] *= corr[mt][hf];
                    const float p0 = __expf((s[mt][nt][2 * hf]     - mst[mt][hf]) * SCALE);
                    const float p1 = __expf((s[mt][nt][2 * hf + 1] - mst[mt][hf]) * SCALE);
                    psum[mt][hf] += p0 + p1;
                    const __half2 hp = __floats2half2_rn(p0, p1);
                    const int q  = wm + mt * 16 + ar + 8 * hf;
                    const int kp = (wn >> 1) + nt * 4 + l3;
                    Kh[q * 68 + kp] = *(const uint32_t*)&hp;
                }
            }
        }
#pragma unroll
        for (int mt = 0; mt < 4; mt++) {
#pragma unroll
            for (int hf = 0; hf < 2; hf++) {
                float sv = psum[mt][hf];
                sv += __shfl_xor_sync(0xFFFFFFFFu, sv, 1);
                sv += __shfl_xor_sync(0xFFFFFFFFu, sv, 2);
                if (l3 == 0) redl[wr * 256 + wc * 64 + mt * 16 + ar + 8 * hf] = sv;
            }
        }
        __syncthreads();   // redl ready + all P writes visible

#pragma unroll
        for (int mt = 0; mt < 4; mt++) {
#pragma unroll
            for (int hf = 0; hf < 2; hf++) {
                const int r = mt * 16 + ar + 8 * hf;
                const float gs = redl[wr * 256 + r] + redl[wr * 256 + 64 + r]
                               + redl[wr * 256 + 128 + r] + redl[wr * 256 + 192 + r];
                lst[mt][hf] = lst[mt][hf] * corr[mt][hf] + gs;
            }
        }

        // ---- O += P @ V (fp16 single MMA, ldmatrix frags) ----
#pragma unroll
        for (int kc = 0; kc < 64; kc += 8) {
            uint32_t bf[4][2];
#pragma unroll
            for (int g = 0; g < 2; g++) {
                const uint32_t bi = (uint32_t)((wn + g * 16 + brow) * 68 + kc + bkp) * 4;
                ldsm4(bf[2*g][0], bf[2*g][1], bf[2*g+1][0], bf[2*g+1][1], smb + 139264 + bi);
            }
#pragma unroll
            for (int mt = 0; mt < 4; mt++) {
                const uint32_t ai = (uint32_t)((wm + mt * 16 + arow) * 68 + kc + akp) * 4;
                uint32_t p0, p1, p2, p3;
                ldsm4(p0, p1, p2, p3, smb + 69632 + ai);
#pragma unroll
                for (int nt = 0; nt < 4; nt++)
                    mma_f16(o[mt][nt], p0, p1, p2, p3, bf[nt][0], bf[nt][1]);
            }
        }
    }

    // ---- epilogue: O/l -> split bf16 -> g_ah/g_al at [q][h*128+d] ----
#pragma unroll
    for (int mt = 0; mt < 4; mt++) {
#pragma unroll
        for (int hf = 0; hf < 2; hf++) {
            const float inv = 1.0f / lst[mt][hf];
            const int q = qb * 128 + wm + mt * 16 + ar + 8 * hf;
#pragma unroll
            for (int nt = 0; nt < 4; nt++) {
                const float o0 = o[mt][nt][2 * hf] * inv;
                const float o1 = o[mt][nt][2 * hf + 1] * inv;
                uint32_t hw, lw;
                split2_bf16(o0, o1, hw, lw);
                const size_t idx = ((size_t)q * DIM + h * HD + wn + nt * 8) / 2 + l3;
                ((uint32_t*)g_ah)[idx] = hw;
                ((uint32_t*)g_al)[idx] = lw;
            }
        }
    }
}

// ---------------------------------------------------------------------------
// Launch
// ---------------------------------------------------------------------------
extern "C" void kernel_launch(void* const* d_in, const int* in_sizes, int n_in,
                              void* d_out, int out_size)
{
    const float* x       = (const float*)d_in[0];
    const float* pe      = (const float*)d_in[1];
    const float* qkv_w   = (const float*)d_in[2];
    const float* q_scale = (const float*)d_in[3];
    const float* k_scale = (const float*)d_in[4];
    const float* proj_w  = (const float*)d_in[5];
    const float* proj_b  = (const float*)d_in[6];
    float* out = (float*)d_out;

    float* qkv;
    __nv_bfloat16 *xh, *xl, *wh, *wl, *pwh, *pwl, *ah, *al;
    cudaGetSymbolAddress((void**)&qkv, g_qkv);
    cudaGetSymbolAddress((void**)&xh,  g_xh);
    cudaGetSymbolAddress((void**)&xl,  g_xl);
    cudaGetSymbolAddress((void**)&wh,  g_wh);
    cudaGetSymbolAddress((void**)&wl,  g_wl);
    cudaGetSymbolAddress((void**)&pwh, g_pwh);
    cudaGetSymbolAddress((void**)&pwl, g_pwl);
    cudaGetSymbolAddress((void**)&ah,  g_ah);
    cudaGetSymbolAddress((void**)&al,  g_al);

    const int GEMM_SMEM  = 81920;
    const int FLASH_SMEM = 178176;
    cudaFuncSetAttribute(gemm_sp<false>, cudaFuncAttributeMaxDynamicSharedMemorySize, GEMM_SMEM);
    cudaFuncSetAttribute(gemm_sp<true>,  cudaFuncAttributeMaxDynamicSharedMemorySize, GEMM_SMEM);
    cudaFuncSetAttribute(flash_kernel,   cudaFuncAttributeMaxDynamicSharedMemorySize, FLASH_SMEM);

    // 0) pre-split inputs
    split_kernel<<<(LQ * DIM / 4 + 255) / 256, 256>>>(x, xh, xl, LQ * DIM / 4);
    split_kernel<<<(QKV_N * DIM / 4 + 255) / 256, 256>>>(qkv_w, wh, wl, QKV_N * DIM / 4);
    split_kernel<<<(DIM * DIM / 4 + 255) / 256, 256>>>(proj_w, pwh, pwl, DIM * DIM / 4);

    // 1) qkv = x @ qkv_w^T
    {
        dim3 grid(QKV_N / 128, LQ / 128);
        gemm_sp<false><<<grid, 256, GEMM_SMEM>>>(xh, xl, wh, wl, qkv, nullptr,
                                                 LQ, QKV_N, DIM, DIM, DIM, QKV_N);
    }

    // 2) RMSNorm + RoPE + splits (q,k) and V -> fp16 transposed
    norm_rope_split<<<3 * NH * LQ, 128>>>(pe, q_scale, k_scale);

    // 3) flash attention -> g_ah/g_al
    {
        dim3 grid(LQ / 128, NH);
        flash_kernel<<<grid, 256, FLASH_SMEM>>>();
    }

    // 4) out = att @ proj_w^T + proj_b
    {
        dim3 grid(DIM / 128, LQ / 128);
        gemm_sp<true><<<grid, 256, GEMM_SMEM>>>(ah, al, pwh, pwl, out, proj_b,
                                                LQ, DIM, DIM, DIM, DIM, DIM);
    }
}

// round 13
// speedup vs baseline: 2.8562x; 1.0017x over previous
#include <cuda_runtime.h>
#include <cuda_bf16.h>
#include <cuda_fp16.h>
#include <cstdint>

// ---------------------------------------------------------------------------
#define LQ    2048
#define DIM   2048
#define NH    16
#define HD    128
#define QKV_N 6144
#define SCALE 0.08838834764831845f   // 1/sqrt(128)

// ---------------------------------------------------------------------------
// Scratch (__device__ globals; allocation-free rule)
// ---------------------------------------------------------------------------
__device__ float g_qkv[(size_t)LQ * QKV_N];                         // fp32 qkv
__device__ __nv_bfloat16 g_xh[(size_t)LQ * DIM],  g_xl[(size_t)LQ * DIM];
__device__ __nv_bfloat16 g_wh[(size_t)QKV_N * DIM], g_wl[(size_t)QKV_N * DIM];
__device__ __nv_bfloat16 g_pwh[(size_t)DIM * DIM],  g_pwl[(size_t)DIM * DIM];
__device__ __nv_bfloat16 g_qh[(size_t)LQ * DIM],  g_ql[(size_t)LQ * DIM];
__device__ __nv_bfloat16 g_kh[(size_t)LQ * DIM],  g_kl[(size_t)LQ * DIM];
__device__ __half        g_vt[(size_t)DIM * LQ];                     // V^T: [h*128+d][L] fp16
__device__ __nv_bfloat16 g_ah[(size_t)LQ * DIM],  g_al[(size_t)LQ * DIM];

// ---------------------------------------------------------------------------
// helpers
// ---------------------------------------------------------------------------
__device__ __forceinline__ void split_bf16(float f, __nv_bfloat16& h, __nv_bfloat16& l) {
    h = __float2bfloat16_rn(f);
    l = __float2bfloat16_rn(f - __bfloat162float(h));
}
__device__ __forceinline__ void split2_bf16(float x, float y, uint32_t& hw, uint32_t& lw) {
    __nv_bfloat16 hx, lx, hy, ly;
    split_bf16(x, hx, lx);
    split_bf16(y, hy, ly);
    __nv_bfloat162 hp, lp;
    hp.x = hx; hp.y = hy;
    lp.x = lx; lp.y = ly;
    hw = *(uint32_t*)&hp;
    lw = *(uint32_t*)&lp;
}
__device__ __forceinline__ uint32_t saddr(const void* p) {
    return (uint32_t)__cvta_generic_to_shared(p);
}
__device__ __forceinline__ void cp16(uint32_t dst, const void* src) {
    asm volatile("cp.async.cg.shared.global [%0], [%1], 16;" :: "r"(dst), "l"(src));
}
#define CP_COMMIT() asm volatile("cp.async.commit_group;")
#define CP_WAIT0()  asm volatile("cp.async.wait_group 0;")
#define CP_WAIT1()  asm volatile("cp.async.wait_group 1;")

// ldmatrix stays volatile (pins smem reads against barriers)
__device__ __forceinline__ void ldsm4(uint32_t& r0, uint32_t& r1, uint32_t& r2, uint32_t& r3,
                                      uint32_t addr) {
    asm volatile("ldmatrix.sync.aligned.m8n8.x4.shared.b16 {%0,%1,%2,%3}, [%4];"
                 : "=r"(r0), "=r"(r1), "=r"(r2), "=r"(r3) : "r"(addr));
}

// NON-volatile mma: pure register op, lets ptxas schedule/interleave freely
__device__ __forceinline__ void mma_bf16(float c[4],
                                         uint32_t a0, uint32_t a1, uint32_t a2, uint32_t a3,
                                         uint32_t b0, uint32_t b1) {
    asm("mma.sync.aligned.m16n8k16.row.col.f32.bf16.bf16.f32 "
        "{%0,%1,%2,%3}, {%4,%5,%6,%7}, {%8,%9}, {%0,%1,%2,%3};"
        : "+f"(c[0]), "+f"(c[1]), "+f"(c[2]), "+f"(c[3])
        : "r"(a0), "r"(a1), "r"(a2), "r"(a3), "r"(b0), "r"(b1));
}
__device__ __forceinline__ void mma_f16(float c[4],
                                        uint32_t a0, uint32_t a1, uint32_t a2, uint32_t a3,
                                        uint32_t b0, uint32_t b1) {
    asm("mma.sync.aligned.m16n8k16.row.col.f32.f16.f16.f32 "
        "{%0,%1,%2,%3}, {%4,%5,%6,%7}, {%8,%9}, {%0,%1,%2,%3};"
        : "+f"(c[0]), "+f"(c[1]), "+f"(c[2]), "+f"(c[3])
        : "r"(a0), "r"(a1), "r"(a2), "r"(a3), "r"(b0), "r"(b1));
}

// ---------------------------------------------------------------------------
// split kernel: fp32[n] -> bf16 hi[n], lo[n]
// ---------------------------------------------------------------------------
__global__ void split_kernel(const float* __restrict__ in,
                             __nv_bfloat16* __restrict__ oh,
                             __nv_bfloat16* __restrict__ ol, int n4)
{
    const int i = blockIdx.x * blockDim.x + threadIdx.x;
    if (i >= n4) return;
    const float4 v = ((const float4*)in)[i];
    uint32_t h01, l01, h23, l23;
    split2_bf16(v.x, v.y, h01, l01);
    split2_bf16(v.z, v.w, h23, l23);
    uint2 th = {h01, h23}, tl = {l01, l23};
    ((uint2*)oh)[i] = th;
    ((uint2*)ol)[i] = tl;
}

// ---------------------------------------------------------------------------
// Split-input bf16x3 GEMM (A@B^T), cp.async 2-stage pipeline, ldmatrix frags.
// Term-major MMA ordering: consecutive MMAs hit different accumulators.
// ---------------------------------------------------------------------------
template<bool BIAS>
__global__ __launch_bounds__(256, 2)
void gemm_sp(const __nv_bfloat16* __restrict__ ah, const __nv_bfloat16* __restrict__ al,
             const __nv_bfloat16* __restrict__ bh, const __nv_bfloat16* __restrict__ bl,
             float* __restrict__ C, const float* __restrict__ bias,
             int M, int N, int K, int lda, int ldb, int ldc)
{
    extern __shared__ uint32_t sm[];
    const uint32_t smb = saddr(sm);
    const int tid  = threadIdx.x;
    const int warp = tid >> 5, lane = tid & 31;
    const int wm = (warp >> 2) * 64, wn = (warp & 3) * 32;
    const int m0 = blockIdx.y * 128, n0 = blockIdx.x * 128;

    const int arow = (lane & 7) + ((lane >> 3) & 1) * 8;
    const int akp  = (lane >> 4) * 4;
    const int brow = (lane & 7) + (lane >> 4) * 8;
    const int bkp  = ((lane >> 3) & 1) * 4;

    float acc[4][4][4];
#pragma unroll
    for (int i = 0; i < 4; i++)
#pragma unroll
        for (int j = 0; j < 4; j++)
#pragma unroll
            for (int r = 0; r < 4; r++) acc[i][j][r] = 0.f;

    auto stage = [&](int s, int k0) {
        uint32_t* B0 = sm + s * 10240;
#pragma unroll
        for (int i = tid; i < 512; i += 256) {
            const int r = i >> 2, c = i & 3;
            cp16(saddr(B0        + r * 20 + c * 4), (const uint4*)(ah + (size_t)(m0 + r) * lda + k0) + c);
            cp16(saddr(B0 + 2560 + r * 20 + c * 4), (const uint4*)(al + (size_t)(m0 + r) * lda + k0) + c);
            cp16(saddr(B0 + 5120 + r * 20 + c * 4), (const uint4*)(bh + (size_t)(n0 + r) * ldb + k0) + c);
            cp16(saddr(B0 + 7680 + r * 20 + c * 4), (const uint4*)(bl + (size_t)(n0 + r) * ldb + k0) + c);
        }
    };

    const int T = K / 32;
    stage(0, 0);
    CP_COMMIT();

    for (int t = 0; t < T; t++) {
        if (t + 1 < T) {
            stage((t + 1) & 1, (t + 1) * 32);
            CP_COMMIT();
            CP_WAIT1();
        } else {
            CP_WAIT0();
        }
        __syncthreads();

        const uint32_t stg = smb + (t & 1) * 40960;

#pragma unroll
        for (int kc = 0; kc < 16; kc += 8) {
            uint32_t bfh[4][2], bfl[4][2];
#pragma unroll
            for (int g = 0; g < 2; g++) {
                const uint32_t bi = (uint32_t)((wn + g * 16 + brow) * 20 + kc + bkp) * 4;
                ldsm4(bfh[2*g][0], bfh[2*g][1], bfh[2*g+1][0], bfh[2*g+1][1], stg + 20480 + bi);
                ldsm4(bfl[2*g][0], bfl[2*g][1], bfl[2*g+1][0], bfl[2*g+1][1], stg + 30720 + bi);
            }
#pragma unroll
            for (int mt = 0; mt < 4; mt++) {
                const uint32_t ai = (uint32_t)((wm + mt * 16 + arow) * 20 + kc + akp) * 4;
                uint32_t ah0, ah1, ah2, ah3, al0, al1, al2, al3;
                ldsm4(ah0, ah1, ah2, ah3, stg + ai);
                ldsm4(al0, al1, al2, al3, stg + 10240 + ai);
                // term-major: consecutive MMAs -> different accumulators
#pragma unroll
                for (int nt = 0; nt < 4; nt++)
                    mma_bf16(acc[mt][nt], ah0, ah1, ah2, ah3, bfl[nt][0], bfl[nt][1]);
#pragma unroll
                for (int nt = 0; nt < 4; nt++)
                    mma_bf16(acc[mt][nt], al0, al1, al2, al3, bfh[nt][0], bfh[nt][1]);
#pragma unroll
                for (int nt = 0; nt < 4; nt++)
                    mma_bf16(acc[mt][nt], ah0, ah1, ah2, ah3, bfh[nt][0], bfh[nt][1]);
            }
        }
        __syncthreads();
    }

    const int cr = lane >> 2, cc = (lane & 3) * 2;
#pragma unroll
    for (int mt = 0; mt < 4; mt++) {
#pragma unroll
        for (int nt = 0; nt < 4; nt++) {
            const int m = m0 + wm + mt * 16 + cr;
            const int n = n0 + wn + nt * 8 + cc;
            float2 v0, v1;
            v0.x = acc[mt][nt][0]; v0.y = acc[mt][nt][1];
            v1.x = acc[mt][nt][2]; v1.y = acc[mt][nt][3];
            if (BIAS) {
                const float b0 = bias[n], b1 = bias[n + 1];
                v0.x += b0; v0.y += b1;
                v1.x += b0; v1.y += b1;
            }
            *(float2*)(C + (size_t)m       * ldc + n) = v0;
            *(float2*)(C + (size_t)(m + 8) * ldc + n) = v1;
        }
    }
}

// ---------------------------------------------------------------------------
// norm_rope_split: RMSNorm+RoPE on q/k -> split bf16; v -> fp16 transposed.
// ---------------------------------------------------------------------------
__global__ void norm_rope_split(const float* __restrict__ pe,
                                const float* __restrict__ q_scale,
                                const float* __restrict__ k_scale)
{
    const int idx = blockIdx.x;
    const int l   = idx & (LQ - 1);
    const int h   = (idx >> 11) & (NH - 1);
    const int qk  = idx >> 15;                  // 0=q, 1=k, 2=v
    const int d   = threadIdx.x;
    const int lane = d & 31, warp = d >> 5;

    const float* row = g_qkv + (size_t)l * QKV_N + qk * DIM + h * HD;
    const float t = row[d];

    if (qk == 2) {
        g_vt[(size_t)(h * HD + d) * LQ + l] = __float2half_rn(t);
        return;
    }

    float ss = t * t;
#pragma unroll
    for (int o = 16; o > 0; o >>= 1) ss += __shfl_xor_sync(0xFFFFFFFFu, ss, o);
    __shared__ float red[4];
    if (lane == 0) red[warp] = ss;
    __syncthreads();
    const float tot = red[0] + red[1] + red[2] + red[3];
    const float rrms = rsqrtf(tot * (1.0f / HD) + 1e-6f);

    const float* scale = qk ? k_scale : q_scale;
    const float tn = t * rrms * scale[d];

    const float other = __shfl_xor_sync(0xFFFFFFFFu, tn, 1);
    const int j = d >> 1, s = d & 1;
    const float* pp = pe + ((size_t)l * (HD / 2) + j) * 4 + s * 2;
    const float te = (s == 0) ? tn : other;
    const float to = (s == 0) ? other : tn;
    const float roped = pp[0] * te + pp[1] * to;

    __shared__ float buf[HD];
    buf[d] = roped;
    __syncthreads();
    if (d < 64) {
        uint32_t hw, lw;
        split2_bf16(buf[2 * d], buf[2 * d + 1], hw, lw);
        const size_t o32 = ((size_t)l * DIM + h * HD) / 2 + d;
        if (qk == 0) { ((uint32_t*)g_qh)[o32] = hw; ((uint32_t*)g_ql)[o32] = lw; }
        else         { ((uint32_t*)g_kh)[o32] = hw; ((uint32_t*)g_kl)[o32] = lw; }
    }
}

// ---------------------------------------------------------------------------
// Flash attention: scores bf16x3 (term-major), online softmax, fp16 PV.
// ---------------------------------------------------------------------------
__global__ __launch_bounds__(256, 1)
void flash_kernel()
{
    extern __shared__ uint32_t sm[];
    const uint32_t smb = saddr(sm);
    uint32_t* Qh = sm;
    uint32_t* Ql = sm + 8704;
    uint32_t* Kh = sm + 17408;   // also Ps (fp16 pairs)
    uint32_t* Kl = sm + 26112;
    uint32_t* Vs = sm + 34816;   // fp16 pairs [d][68]
    float* redm = (float*)(sm + 43520);
    float* redl = (float*)(sm + 44032);

    const int tid  = threadIdx.x;
    const int warp = tid >> 5, lane = tid & 31;
    const int wm = (warp >> 2) * 64, wn = (warp & 3) * 32;
    const int wr = warp >> 2, wc = warp & 3;
    const int qb = blockIdx.x, h = blockIdx.y;
    const int ar = lane >> 2;
    const int l3 = lane & 3;

    const int arow = (lane & 7) + ((lane >> 3) & 1) * 8;
    const int akp  = (lane >> 4) * 4;
    const int brow = (lane & 7) + (lane >> 4) * 8;
    const int bkp  = ((lane >> 3) & 1) * 4;

#pragma unroll
    for (int i = tid; i < 2048; i += 256) {
        const int r = i >> 4, c = i & 15;
        const size_t off = ((size_t)(qb * 128 + r) * DIM + h * HD) / 2;
        cp16(saddr(Qh + r * 68 + c * 4), (const uint4*)((const uint32_t*)g_qh + off) + c);
        cp16(saddr(Ql + r * 68 + c * 4), (const uint4*)((const uint32_t*)g_ql + off) + c);
    }
    CP_COMMIT();

    float o[4][4][4];
    float s[4][4][4];
    float mst[4][2], lst[4][2], corr[4][2];
#pragma unroll
    for (int i = 0; i < 4; i++) {
#pragma unroll
        for (int j = 0; j < 4; j++)
#pragma unroll
            for (int r = 0; r < 4; r++) o[i][j][r] = 0.f;
        mst[i][0] = -1e30f; mst[i][1] = -1e30f;
        lst[i][0] = 0.f;    lst[i][1] = 0.f;
    }

    for (int kb = 0; kb < 16; kb++) {
        if (kb) __syncthreads();

#pragma unroll
        for (int i = tid; i < 2048; i += 256) {
            const int r = i >> 4, c = i & 15;
            const size_t off = ((size_t)(kb * 128 + r) * DIM + h * HD) / 2;
            cp16(saddr(Kh + r * 68 + c * 4), (const uint4*)((const uint32_t*)g_kh + off) + c);
            cp16(saddr(Kl + r * 68 + c * 4), (const uint4*)((const uint32_t*)g_kl + off) + c);
        }
#pragma unroll
        for (int i = tid; i < 2048; i += 256) {
            const int r = i >> 4, c = i & 15;
            const size_t off = ((size_t)(h * HD + r) * LQ + kb * 128) / 2;
            cp16(saddr(Vs + r * 68 + c * 4), (const uint4*)((const uint32_t*)g_vt + off) + c);
        }
        CP_COMMIT();
        CP_WAIT0();
        __syncthreads();

#pragma unroll
        for (int i = 0; i < 4; i++)
#pragma unroll
            for (int j = 0; j < 4; j++)
#pragma unroll
                for (int r = 0; r < 4; r++) s[i][j][r] = 0.f;

#pragma unroll
        for (int kc = 0; kc < 64; kc += 8) {
            uint32_t bfh[4][2], bfl[4][2];
#pragma unroll
            for (int g = 0; g < 2; g++) {
                const uint32_t bi = (uint32_t)((wn + g * 16 + brow) * 68 + kc + bkp) * 4;
                ldsm4(bfh[2*g][0], bfh[2*g][1], bfh[2*g+1][0], bfh[2*g+1][1], smb + 69632 + bi);
                ldsm4(bfl[2*g][0], bfl[2*g][1], bfl[2*g+1][0], bfl[2*g+1][1], smb + 104448 + bi);
            }
#pragma unroll
            for (int mt = 0; mt < 4; mt++) {
                const uint32_t ai = (uint32_t)((wm + mt * 16 + arow) * 68 + kc + akp) * 4;
                uint32_t qh0, qh1, qh2, qh3, ql0, ql1, ql2, ql3;
                ldsm4(qh0, qh1, qh2, qh3, smb + ai);
                ldsm4(ql0, ql1, ql2, ql3, smb + 34816 + ai);
                // term-major ordering
#pragma unroll
                for (int nt = 0; nt < 4; nt++)
                    mma_bf16(s[mt][nt], qh0, qh1, qh2, qh3, bfl[nt][0], bfl[nt][1]);
#pragma unroll
                for (int nt = 0; nt < 4; nt++)
                    mma_bf16(s[mt][nt], ql0, ql1, ql2, ql3, bfh[nt][0], bfh[nt][1]);
#pragma unroll
                for (int nt = 0; nt < 4; nt++)
                    mma_bf16(s[mt][nt], qh0, qh1, qh2, qh3, bfh[nt][0], bfh[nt][1]);
            }
        }

#pragma unroll
        for (int mt = 0; mt < 4; mt++) {
#pragma unroll
            for (int hf = 0; hf < 2; hf++) {
                float mx = -1e30f;
#pragma unroll
                for (int nt = 0; nt < 4; nt++) {
                    mx = fmaxf(mx, s[mt][nt][2 * hf]);
                    mx = fmaxf(mx, s[mt][nt][2 * hf + 1]);
                }
                mx = fmaxf(mx, __shfl_xor_sync(0xFFFFFFFFu, mx, 1));
                mx = fmaxf(mx, __shfl_xor_sync(0xFFFFFFFFu, mx, 2));
                if (l3 == 0) redm[wr * 256 + wc * 64 + mt * 16 + ar + 8 * hf] = mx;
            }
        }
        __syncthreads();

        float psum[4][2];
#pragma unroll
        for (int mt = 0; mt < 4; mt++) {
#pragma unroll
            for (int hf = 0; hf < 2; hf++) {
                const int r = mt * 16 + ar + 8 * hf;
                float gm = redm[wr * 256 + r];
                gm = fmaxf(gm, redm[wr * 256 + 64 + r]);
                gm = fmaxf(gm, redm[wr * 256 + 128 + r]);
                gm = fmaxf(gm, redm[wr * 256 + 192 + r]);
                const float mnew = fmaxf(mst[mt][hf], gm);
                corr[mt][hf] = __expf((mst[mt][hf] - mnew) * SCALE);
                mst[mt][hf] = mnew;
                psum[mt][hf] = 0.f;
            }
        }

#pragma unroll
        for (int mt = 0; mt < 4; mt++) {
#pragma unroll
            for (int nt = 0; nt < 4; nt++) {
#pragma unroll
                for (int hf = 0; hf < 2; hf++) {
                    o[mt][nt][2 * hf]     *= corr[mt][hf];
                    o[mt][nt][2 * hf + 1] *= corr[mt][hf];
                    const float p0 = __expf((s[mt][nt][2 * hf]     - mst[mt][hf]) * SCALE);
                    const float p1 = __expf((s[mt][nt][2 * hf + 1] - mst[mt][hf]) * SCALE);
                    psum[mt][hf] += p0 + p1;
                    const __half2 hp = __floats2half2_rn(p0, p1);
                    const int q  = wm + mt * 16 + ar + 8 * hf;
                    const int kp = (wn >> 1) + nt * 4 + l3;
                    Kh[q * 68 + kp] = *(const uint32_t*)&hp;
                }
            }
        }
#pragma unroll
        for (int mt = 0; mt < 4; mt++) {
#pragma unroll
            for (int hf = 0; hf < 2; hf++) {
                float sv = psum[mt][hf];
                sv += __shfl_xor_sync(0xFFFFFFFFu, sv, 1);
                sv += __shfl_xor_sync(0xFFFFFFFFu, sv, 2);
                if (l3 == 0) redl[wr * 256 + wc * 64 + mt * 16 + ar + 8 * hf] = sv;
            }
        }
        __syncthreads();

#pragma unroll
        for (int mt = 0; mt < 4; mt++) {
#pragma unroll
            for (int hf = 0; hf < 2; hf++) {
                const int r = mt * 16 + ar + 8 * hf;
                const float gs = redl[wr * 256 + r] + redl[wr * 256 + 64 + r]
                               + redl[wr * 256 + 128 + r] + redl[wr * 256 + 192 + r];
                lst[mt][hf] = lst[mt][hf] * corr[mt][hf] + gs;
            }
        }

#pragma unroll
        for (int kc = 0; kc < 64; kc += 8) {
            uint32_t bf[4][2];
#pragma unroll
            for (int g = 0; g < 2; g++) {
                const uint32_t bi = (uint32_t)((wn + g * 16 + brow) * 68 + kc + bkp) * 4;
                ldsm4(bf[2*g][0], bf[2*g][1], bf[2*g+1][0], bf[2*g+1][1], smb + 139264 + bi);
            }
#pragma unroll
            for (int mt = 0; mt < 4; mt++) {
                const uint32_t ai = (uint32_t)((wm + mt * 16 + arow) * 68 + kc + akp) * 4;
                uint32_t p0, p1, p2, p3;
                ldsm4(p0, p1, p2, p3, smb + 69632 + ai);
#pragma unroll
                for (int nt = 0; nt < 4; nt++)
                    mma_f16(o[mt][nt], p0, p1, p2, p3, bf[nt][0], bf[nt][1]);
            }
        }
    }

#pragma unroll
    for (int mt = 0; mt < 4; mt++) {
#pragma unroll
        for (int hf = 0; hf < 2; hf++) {
            const float inv = 1.0f / lst[mt][hf];
            const int q = qb * 128 + wm + mt * 16 + ar + 8 * hf;
#pragma unroll
            for (int nt = 0; nt < 4; nt++) {
                const float o0 = o[mt][nt][2 * hf] * inv;
                const float o1 = o[mt][nt][2 * hf + 1] * inv;
                uint32_t hw, lw;
                split2_bf16(o0, o1, hw, lw);
                const size_t idx = ((size_t)q * DIM + h * HD + wn + nt * 8) / 2 + l3;
                ((uint32_t*)g_ah)[idx] = hw;
                ((uint32_t*)g_al)[idx] = lw;
            }
        }
    }
}

// ---------------------------------------------------------------------------
// Launch
// ---------------------------------------------------------------------------
extern "C" void kernel_launch(void* const* d_in, const int* in_sizes, int n_in,
                              void* d_out, int out_size)
{
    const float* x       = (const float*)d_in[0];
    const float* pe      = (const float*)d_in[1];
    const float* qkv_w   = (const float*)d_in[2];
    const float* q_scale = (const float*)d_in[3];
    const float* k_scale = (const float*)d_in[4];
    const float* proj_w  = (const float*)d_in[5];
    const float* proj_b  = (const float*)d_in[6];
    float* out = (float*)d_out;

    float* qkv;
    __nv_bfloat16 *xh, *xl, *wh, *wl, *pwh, *pwl, *ah, *al;
    cudaGetSymbolAddress((void**)&qkv, g_qkv);
    cudaGetSymbolAddress((void**)&xh,  g_xh);
    cudaGetSymbolAddress((void**)&xl,  g_xl);
    cudaGetSymbolAddress((void**)&wh,  g_wh);
    cudaGetSymbolAddress((void**)&wl,  g_wl);
    cudaGetSymbolAddress((void**)&pwh, g_pwh);
    cudaGetSymbolAddress((void**)&pwl, g_pwl);
    cudaGetSymbolAddress((void**)&ah,  g_ah);
    cudaGetSymbolAddress((void**)&al,  g_al);

    const int GEMM_SMEM  = 81920;
    const int FLASH_SMEM = 178176;
    cudaFuncSetAttribute(gemm_sp<false>, cudaFuncAttributeMaxDynamicSharedMemorySize, GEMM_SMEM);
    cudaFuncSetAttribute(gemm_sp<true>,  cudaFuncAttributeMaxDynamicSharedMemorySize, GEMM_SMEM);
    cudaFuncSetAttribute(flash_kernel,   cudaFuncAttributeMaxDynamicSharedMemorySize, FLASH_SMEM);

    // 0) pre-split inputs
    split_kernel<<<(LQ * DIM / 4 + 255) / 256, 256>>>(x, xh, xl, LQ * DIM / 4);
    split_kernel<<<(QKV_N * DIM / 4 + 255) / 256, 256>>>(qkv_w, wh, wl, QKV_N * DIM / 4);
    split_kernel<<<(DIM * DIM / 4 + 255) / 256, 256>>>(proj_w, pwh, pwl, DIM * DIM / 4);

    // 1) qkv = x @ qkv_w^T
    {
        dim3 grid(QKV_N / 128, LQ / 128);
        gemm_sp<false><<<grid, 256, GEMM_SMEM>>>(xh, xl, wh, wl, qkv, nullptr,
                                                 LQ, QKV_N, DIM, DIM, DIM, QKV_N);
    }

    // 2) RMSNorm + RoPE + splits (q,k) and V -> fp16 transposed
    norm_rope_split<<<3 * NH * LQ, 128>>>(pe, q_scale, k_scale);

    // 3) flash attention -> g_ah/g_al
    {
        dim3 grid(LQ / 128, NH);
        flash_kernel<<<grid, 256, FLASH_SMEM>>>();
    }

    // 4) out = att @ proj_w^T + proj_b
    {
        dim3 grid(DIM / 128, LQ / 128);
        gemm_sp<true><<<grid, 256, GEMM_SMEM>>>(ah, al, pwh, pwl, out, proj_b,
                                                LQ, DIM, DIM, DIM, DIM, DIM);
    }
}

// round 15
// speedup vs baseline: 4.0492x; 1.4177x over previous
#include <cuda_runtime.h>
#include <cuda_bf16.h>
#include <cuda_fp16.h>
#include <cstdint>

// ---------------------------------------------------------------------------
#define LQ    2048
#define DIM   2048
#define NH    16
#define HD    128
#define QKV_N 6144
#define SCALE 0.08838834764831845f   // 1/sqrt(128)

// ---------------------------------------------------------------------------
// Scratch (__device__ globals; allocation-free rule)
// ---------------------------------------------------------------------------
__device__ float  g_qkv[(size_t)LQ * QKV_N];                  // fp32 qkv
__device__ __half g_xh[(size_t)LQ * DIM],  g_xl[(size_t)LQ * DIM];   // x split fp16
__device__ __half g_wh[(size_t)QKV_N * DIM];                  // qkv_w rounded fp16
__device__ __half g_pwh[(size_t)DIM * DIM];                   // proj_w rounded fp16
__device__ __half g_qs[(size_t)LQ * DIM],  g_ks[(size_t)LQ * DIM];   // q,k fp16
__device__ __half g_vt[(size_t)DIM * LQ];                     // V^T fp16
__device__ __half g_ah[(size_t)LQ * DIM],  g_al[(size_t)LQ * DIM];   // attn out split fp16

// ---------------------------------------------------------------------------
// helpers
// ---------------------------------------------------------------------------
__device__ __forceinline__ void split2_f16(float x, float y, uint32_t& hw, uint32_t& lw) {
    __half hx = __float2half_rn(x);
    __half hy = __float2half_rn(y);
    __half lx = __float2half_rn(x - __half2float(hx));
    __half ly = __float2half_rn(y - __half2float(hy));
    __half2 hp, lp;
    hp.x = hx; hp.y = hy;
    lp.x = lx; lp.y = ly;
    hw = *(uint32_t*)&hp;
    lw = *(uint32_t*)&lp;
}
__device__ __forceinline__ uint32_t round2_f16(float x, float y) {
    __half2 p = __floats2half2_rn(x, y);
    return *(uint32_t*)&p;
}
__device__ __forceinline__ uint32_t saddr(const void* p) {
    return (uint32_t)__cvta_generic_to_shared(p);
}
__device__ __forceinline__ void cp16(uint32_t dst, const void* src) {
    asm volatile("cp.async.cg.shared.global [%0], [%1], 16;" :: "r"(dst), "l"(src));
}
#define CP_COMMIT() asm volatile("cp.async.commit_group;")
#define CP_WAIT0()  asm volatile("cp.async.wait_group 0;")
#define CP_WAIT1()  asm volatile("cp.async.wait_group 1;")

__device__ __forceinline__ void ldsm4(uint32_t& r0, uint32_t& r1, uint32_t& r2, uint32_t& r3,
                                      uint32_t addr) {
    asm volatile("ldmatrix.sync.aligned.m8n8.x4.shared.b16 {%0,%1,%2,%3}, [%4];"
                 : "=r"(r0), "=r"(r1), "=r"(r2), "=r"(r3) : "r"(addr));
}
__device__ __forceinline__ void mma_f16(float c[4],
                                        uint32_t a0, uint32_t a1, uint32_t a2, uint32_t a3,
                                        uint32_t b0, uint32_t b1) {
    asm("mma.sync.aligned.m16n8k16.row.col.f32.f16.f16.f32 "
        "{%0,%1,%2,%3}, {%4,%5,%6,%7}, {%8,%9}, {%0,%1,%2,%3};"
        : "+f"(c[0]), "+f"(c[1]), "+f"(c[2]), "+f"(c[3])
        : "r"(a0), "r"(a1), "r"(a2), "r"(a3), "r"(b0), "r"(b1));
}

// ---------------------------------------------------------------------------
// pre-processing kernels
// ---------------------------------------------------------------------------
__global__ void split_f16_kernel(const float* __restrict__ in,
                                 __half* __restrict__ oh, __half* __restrict__ ol, int n4)
{
    const int i = blockIdx.x * blockDim.x + threadIdx.x;
    if (i >= n4) return;
    const float4 v = ((const float4*)in)[i];
    uint32_t h01, l01, h23, l23;
    split2_f16(v.x, v.y, h01, l01);
    split2_f16(v.z, v.w, h23, l23);
    uint2 th = {h01, h23}, tl = {l01, l23};
    ((uint2*)oh)[i] = th;
    ((uint2*)ol)[i] = tl;
}
__global__ void round_f16_kernel(const float* __restrict__ in,
                                 __half* __restrict__ oh, int n4)
{
    const int i = blockIdx.x * blockDim.x + threadIdx.x;
    if (i >= n4) return;
    const float4 v = ((const float4*)in)[i];
    uint2 t = {round2_f16(v.x, v.y), round2_f16(v.z, v.w)};
    ((uint2*)oh)[i] = t;
}

// ---------------------------------------------------------------------------
// fp16x2 A-split GEMM (A@B^T): C = (Ah+Al) @ Bh  (+bias)
// = exact-A x fp16(B). Tiles 128x128x32, 8 warps 2x4, cp.async 2-stage.
// Stage (u32): Ah[128][20] | Al[128][20] | Bh[128][20] = 7680 u32 = 30720 B.
// ---------------------------------------------------------------------------
template<bool BIAS>
__global__ __launch_bounds__(256, 2)
void gemm_sp(const __half* __restrict__ ah, const __half* __restrict__ al,
             const __half* __restrict__ bh,
             float* __restrict__ C, const float* __restrict__ bias,
             int M, int N, int K, int lda, int ldb, int ldc)
{
    extern __shared__ uint32_t sm[];
    const uint32_t smb = saddr(sm);
    const int tid  = threadIdx.x;
    const int warp = tid >> 5, lane = tid & 31;
    const int wm = (warp >> 2) * 64, wn = (warp & 3) * 32;
    const int m0 = blockIdx.y * 128, n0 = blockIdx.x * 128;

    const int arow = (lane & 7) + ((lane >> 3) & 1) * 8;
    const int akp  = (lane >> 4) * 4;
    const int brow = (lane & 7) + (lane >> 4) * 8;
    const int bkp  = ((lane >> 3) & 1) * 4;

    float acc[4][4][4];
#pragma unroll
    for (int i = 0; i < 4; i++)
#pragma unroll
        for (int j = 0; j < 4; j++)
#pragma unroll
            for (int r = 0; r < 4; r++) acc[i][j][r] = 0.f;

    auto stage = [&](int s, int k0) {
        uint32_t* B0 = sm + s * 7680;
#pragma unroll
        for (int i = tid; i < 512; i += 256) {
            const int r = i >> 2, c = i & 3;
            cp16(saddr(B0        + r * 20 + c * 4), (const uint4*)(ah + (size_t)(m0 + r) * lda + k0) + c);
            cp16(saddr(B0 + 2560 + r * 20 + c * 4), (const uint4*)(al + (size_t)(m0 + r) * lda + k0) + c);
            cp16(saddr(B0 + 5120 + r * 20 + c * 4), (const uint4*)(bh + (size_t)(n0 + r) * ldb + k0) + c);
        }
    };

    const int T = K / 32;
    stage(0, 0);
    CP_COMMIT();

    for (int t = 0; t < T; t++) {
        if (t + 1 < T) {
            stage((t + 1) & 1, (t + 1) * 32);
            CP_COMMIT();
            CP_WAIT1();
        } else {
            CP_WAIT0();
        }
        __syncthreads();

        const uint32_t stg = smb + (t & 1) * 30720;

#pragma unroll
        for (int kc = 0; kc < 16; kc += 8) {
            uint32_t bf[4][2];
#pragma unroll
            for (int g = 0; g < 2; g++) {
                const uint32_t bi = (uint32_t)((wn + g * 16 + brow) * 20 + kc + bkp) * 4;
                ldsm4(bf[2*g][0], bf[2*g][1], bf[2*g+1][0], bf[2*g+1][1], stg + 20480 + bi);
            }
#pragma unroll
            for (int mt = 0; mt < 4; mt++) {
                const uint32_t ai = (uint32_t)((wm + mt * 16 + arow) * 20 + kc + akp) * 4;
                uint32_t ah0, ah1, ah2, ah3, al0, al1, al2, al3;
                ldsm4(ah0, ah1, ah2, ah3, stg + ai);
                ldsm4(al0, al1, al2, al3, stg + 10240 + ai);
                // small term first, dominant last; term-major for dependency spacing
#pragma unroll
                for (int nt = 0; nt < 4; nt++)
                    mma_f16(acc[mt][nt], al0, al1, al2, al3, bf[nt][0], bf[nt][1]);
#pragma unroll
                for (int nt = 0; nt < 4; nt++)
                    mma_f16(acc[mt][nt], ah0, ah1, ah2, ah3, bf[nt][0], bf[nt][1]);
            }
        }
        __syncthreads();
    }

    const int cr = lane >> 2, cc = (lane & 3) * 2;
#pragma unroll
    for (int mt = 0; mt < 4; mt++) {
#pragma unroll
        for (int nt = 0; nt < 4; nt++) {
            const int m = m0 + wm + mt * 16 + cr;
            const int n = n0 + wn + nt * 8 + cc;
            float2 v0, v1;
            v0.x = acc[mt][nt][0]; v0.y = acc[mt][nt][1];
            v1.x = acc[mt][nt][2]; v1.y = acc[mt][nt][3];
            if (BIAS) {
                const float b0 = bias[n], b1 = bias[n + 1];
                v0.x += b0; v0.y += b1;
                v1.x += b0; v1.y += b1;
            }
            *(float2*)(C + (size_t)m       * ldc + n) = v0;
            *(float2*)(C + (size_t)(m + 8) * ldc + n) = v1;
        }
    }
}

// ---------------------------------------------------------------------------
// norm_rope_split: RMSNorm+RoPE on q/k -> fp16; v -> fp16 transposed.
// ---------------------------------------------------------------------------
__global__ void norm_rope_split(const float* __restrict__ pe,
                                const float* __restrict__ q_scale,
                                const float* __restrict__ k_scale)
{
    const int idx = blockIdx.x;
    const int l   = idx & (LQ - 1);
    const int h   = (idx >> 11) & (NH - 1);
    const int qk  = idx >> 15;                  // 0=q, 1=k, 2=v
    const int d   = threadIdx.x;
    const int lane = d & 31, warp = d >> 5;

    const float* row = g_qkv + (size_t)l * QKV_N + qk * DIM + h * HD;
    const float t = row[d];

    if (qk == 2) {
        g_vt[(size_t)(h * HD + d) * LQ + l] = __float2half_rn(t);
        return;
    }

    float ss = t * t;
#pragma unroll
    for (int o = 16; o > 0; o >>= 1) ss += __shfl_xor_sync(0xFFFFFFFFu, ss, o);
    __shared__ float red[4];
    if (lane == 0) red[warp] = ss;
    __syncthreads();
    const float tot = red[0] + red[1] + red[2] + red[3];
    const float rrms = rsqrtf(tot * (1.0f / HD) + 1e-6f);

    const float* scale = qk ? k_scale : q_scale;
    const float tn = t * rrms * scale[d];

    const float other = __shfl_xor_sync(0xFFFFFFFFu, tn, 1);
    const int j = d >> 1, s = d & 1;
    const float* pp = pe + ((size_t)l * (HD / 2) + j) * 4 + s * 2;
    const float te = (s == 0) ? tn : other;
    const float to = (s == 0) ? other : tn;
    const float roped = pp[0] * te + pp[1] * to;

    __shared__ float buf[HD];
    buf[d] = roped;
    __syncthreads();
    if (d < 64) {
        const uint32_t w = round2_f16(buf[2 * d], buf[2 * d + 1]);
        const size_t o32 = ((size_t)l * DIM + h * HD) / 2 + d;
        if (qk == 0) ((uint32_t*)g_qs)[o32] = w;
        else         ((uint32_t*)g_ks)[o32] = w;
    }
}

// ---------------------------------------------------------------------------
// Flash attention: all-fp16 scores (1 MMA), online softmax, fp16 PV.
// smem (u32): Qs[128*68] | Ks[128*68] (->Ps) | Vs[128*68] | redm | redl
// = 27136 u32 = 108544 B.
// ---------------------------------------------------------------------------
__global__ __launch_bounds__(256, 1)
void flash_kernel()
{
    extern __shared__ uint32_t sm[];
    const uint32_t smb = saddr(sm);
    uint32_t* Qs = sm;
    uint32_t* Ks = sm + 8704;    // also Ps (fp16 pairs)
    uint32_t* Vs = sm + 17408;
    float* redm = (float*)(sm + 26112);
    float* redl = (float*)(sm + 26624);

    const int tid  = threadIdx.x;
    const int warp = tid >> 5, lane = tid & 31;
    const int wm = (warp >> 2) * 64, wn = (warp & 3) * 32;
    const int wr = warp >> 2, wc = warp & 3;
    const int qb = blockIdx.x, h = blockIdx.y;
    const int ar = lane >> 2;
    const int l3 = lane & 3;

    const int arow = (lane & 7) + ((lane >> 3) & 1) * 8;
    const int akp  = (lane >> 4) * 4;
    const int brow = (lane & 7) + (lane >> 4) * 8;
    const int bkp  = ((lane >> 3) & 1) * 4;

    // stage Q block
#pragma unroll
    for (int i = tid; i < 2048; i += 256) {
        const int r = i >> 4, c = i & 15;
        const size_t off = ((size_t)(qb * 128 + r) * DIM + h * HD) / 2;
        cp16(saddr(Qs + r * 68 + c * 4), (const uint4*)((const uint32_t*)g_qs + off) + c);
    }
    CP_COMMIT();

    float o[4][4][4];
    float s[4][4][4];
    float mst[4][2], lst[4][2], corr[4][2];
#pragma unroll
    for (int i = 0; i < 4; i++) {
#pragma unroll
        for (int j = 0; j < 4; j++)
#pragma unroll
            for (int r = 0; r < 4; r++) o[i][j][r] = 0.f;
        mst[i][0] = -1e30f; mst[i][1] = -1e30f;
        lst[i][0] = 0.f;    lst[i][1] = 0.f;
    }

    for (int kb = 0; kb < 16; kb++) {
        if (kb) __syncthreads();   // prior PV reads of Ps/Vs done before restaging

#pragma unroll
        for (int i = tid; i < 2048; i += 256) {
            const int r = i >> 4, c = i & 15;
            const size_t off = ((size_t)(kb * 128 + r) * DIM + h * HD) / 2;
            cp16(saddr(Ks + r * 68 + c * 4), (const uint4*)((const uint32_t*)g_ks + off) + c);
        }
#pragma unroll
        for (int i = tid; i < 2048; i += 256) {
            const int r = i >> 4, c = i & 15;
            const size_t off = ((size_t)(h * HD + r) * LQ + kb * 128) / 2;
            cp16(saddr(Vs + r * 68 + c * 4), (const uint4*)((const uint32_t*)g_vt + off) + c);
        }
        CP_COMMIT();
        CP_WAIT0();
        __syncthreads();

        // ---- S = Q @ K^T (fp16 single-MMA) ----
#pragma unroll
        for (int i = 0; i < 4; i++)
#pragma unroll
            for (int j = 0; j < 4; j++)
#pragma unroll
                for (int r = 0; r < 4; r++) s[i][j][r] = 0.f;

#pragma unroll
        for (int kc = 0; kc < 64; kc += 8) {
            uint32_t bf[4][2];
#pragma unroll
            for (int g = 0; g < 2; g++) {
                const uint32_t bi = (uint32_t)((wn + g * 16 + brow) * 68 + kc + bkp) * 4;
                ldsm4(bf[2*g][0], bf[2*g][1], bf[2*g+1][0], bf[2*g+1][1], smb + 34816 + bi);
            }
#pragma unroll
            for (int mt = 0; mt < 4; mt++) {
                const uint32_t ai = (uint32_t)((wm + mt * 16 + arow) * 68 + kc + akp) * 4;
                uint32_t q0, q1, q2, q3;
                ldsm4(q0, q1, q2, q3, smb + ai);
#pragma unroll
                for (int nt = 0; nt < 4; nt++)
                    mma_f16(s[mt][nt], q0, q1, q2, q3, bf[nt][0], bf[nt][1]);
            }
        }

        // ---- row max ----
#pragma unroll
        for (int mt = 0; mt < 4; mt++) {
#pragma unroll
            for (int hf = 0; hf < 2; hf++) {
                float mx = -1e30f;
#pragma unroll
                for (int nt = 0; nt < 4; nt++) {
                    mx = fmaxf(mx, s[mt][nt][2 * hf]);
                    mx = fmaxf(mx, s[mt][nt][2 * hf + 1]);
                }
                mx = fmaxf(mx, __shfl_xor_sync(0xFFFFFFFFu, mx, 1));
                mx = fmaxf(mx, __shfl_xor_sync(0xFFFFFFFFu, mx, 2));
                if (l3 == 0) redm[wr * 256 + wc * 64 + mt * 16 + ar + 8 * hf] = mx;
            }
        }
        __syncthreads();   // also: all S-loop LDSM of Ks complete before Ps writes

        float psum[4][2];
#pragma unroll
        for (int mt = 0; mt < 4; mt++) {
#pragma unroll
            for (int hf = 0; hf < 2; hf++) {
                const int r = mt * 16 + ar + 8 * hf;
                float gm = redm[wr * 256 + r];
                gm = fmaxf(gm, redm[wr * 256 + 64 + r]);
                gm = fmaxf(gm, redm[wr * 256 + 128 + r]);
                gm = fmaxf(gm, redm[wr * 256 + 192 + r]);
                const float mnew = fmaxf(mst[mt][hf], gm);
                corr[mt][hf] = __expf((mst[mt][hf] - mnew) * SCALE);
                mst[mt][hf] = mnew;
                psum[mt][hf] = 0.f;
            }
        }

        // rescale O, exponentiate S -> P (fp16 into Ps=Ks), partial sums
#pragma unroll
        for (int mt = 0; mt < 4; mt++) {
#pragma unroll
            for (int nt = 0; nt < 4; nt++) {
#pragma unroll
                for (int hf = 0; hf < 2; hf++) {
                    o[mt][nt][2 * hf]     *= corr[mt][hf];
                    o[mt][nt][2 * hf + 1] *= corr[mt][hf];
                    const float p0 = __expf((s[mt][nt][2 * hf]     - mst[mt][hf]) * SCALE);
                    const float p1 = __expf((s[mt][nt][2 * hf + 1] - mst[mt][hf]) * SCALE);
                    psum[mt][hf] += p0 + p1;
                    const __half2 hp = __floats2half2_rn(p0, p1);
                    const int q  = wm + mt * 16 + ar + 8 * hf;
                    const int kp = (wn >> 1) + nt * 4 + l3;
                    Ks[q * 68 + kp] = *(const uint32_t*)&hp;
                }
            }
        }
#pragma unroll
        for (int mt = 0; mt < 4; mt++) {
#pragma unroll
            for (int hf = 0; hf < 2; hf++) {
                float sv = psum[mt][hf];
                sv += __shfl_xor_sync(0xFFFFFFFFu, sv, 1);
                sv += __shfl_xor_sync(0xFFFFFFFFu, sv, 2);
                if (l3 == 0) redl[wr * 256 + wc * 64 + mt * 16 + ar + 8 * hf] = sv;
            }
        }
        __syncthreads();   // redl ready + P writes visible

#pragma unroll
        for (int mt = 0; mt < 4; mt++) {
#pragma unroll
            for (int hf = 0; hf < 2; hf++) {
                const int r = mt * 16 + ar + 8 * hf;
                const float gs = redl[wr * 256 + r] + redl[wr * 256 + 64 + r]
                               + redl[wr * 256 + 128 + r] + redl[wr * 256 + 192 + r];
                lst[mt][hf] = lst[mt][hf] * corr[mt][hf] + gs;
            }
        }

        // ---- O += P @ V (fp16) ----
#pragma unroll
        for (int kc = 0; kc < 64; kc += 8) {
            uint32_t bf[4][2];
#pragma unroll
            for (int g = 0; g < 2; g++) {
                const uint32_t bi = (uint32_t)((wn + g * 16 + brow) * 68 + kc + bkp) * 4;
                ldsm4(bf[2*g][0], bf[2*g][1], bf[2*g+1][0], bf[2*g+1][1], smb + 69632 + bi);
            }
#pragma unroll
            for (int mt = 0; mt < 4; mt++) {
                const uint32_t ai = (uint32_t)((wm + mt * 16 + arow) * 68 + kc + akp) * 4;
                uint32_t p0, p1, p2, p3;
                ldsm4(p0, p1, p2, p3, smb + 34816 + ai);
#pragma unroll
                for (int nt = 0; nt < 4; nt++)
                    mma_f16(o[mt][nt], p0, p1, p2, p3, bf[nt][0], bf[nt][1]);
            }
        }
    }

    // ---- epilogue: O/l -> fp16 split -> g_ah/g_al ----
#pragma unroll
    for (int mt = 0; mt < 4; mt++) {
#pragma unroll
        for (int hf = 0; hf < 2; hf++) {
            const float inv = 1.0f / lst[mt][hf];
            const int q = qb * 128 + wm + mt * 16 + ar + 8 * hf;
#pragma unroll
            for (int nt = 0; nt < 4; nt++) {
                const float o0 = o[mt][nt][2 * hf] * inv;
                const float o1 = o[mt][nt][2 * hf + 1] * inv;
                uint32_t hw, lw;
                split2_f16(o0, o1, hw, lw);
                const size_t idx = ((size_t)q * DIM + h * HD + wn + nt * 8) / 2 + l3;
                ((uint32_t*)g_ah)[idx] = hw;
                ((uint32_t*)g_al)[idx] = lw;
            }
        }
    }
}

// ---------------------------------------------------------------------------
// Launch
// ---------------------------------------------------------------------------
extern "C" void kernel_launch(void* const* d_in, const int* in_sizes, int n_in,
                              void* d_out, int out_size)
{
    const float* x       = (const float*)d_in[0];
    const float* pe      = (const float*)d_in[1];
    const float* qkv_w   = (const float*)d_in[2];
    const float* q_scale = (const float*)d_in[3];
    const float* k_scale = (const float*)d_in[4];
    const float* proj_w  = (const float*)d_in[5];
    const float* proj_b  = (const float*)d_in[6];
    float* out = (float*)d_out;

    float* qkv;
    __half *xh, *xl, *wh, *pwh, *ah, *al;
    cudaGetSymbolAddress((void**)&qkv, g_qkv);
    cudaGetSymbolAddress((void**)&xh,  g_xh);
    cudaGetSymbolAddress((void**)&xl,  g_xl);
    cudaGetSymbolAddress((void**)&wh,  g_wh);
    cudaGetSymbolAddress((void**)&pwh, g_pwh);
    cudaGetSymbolAddress((void**)&ah,  g_ah);
    cudaGetSymbolAddress((void**)&al,  g_al);

    const int GEMM_SMEM  = 61440;    // 2 x 30720
    const int FLASH_SMEM = 108544;   // 27136 u32
    cudaFuncSetAttribute(gemm_sp<false>, cudaFuncAttributeMaxDynamicSharedMemorySize, GEMM_SMEM);
    cudaFuncSetAttribute(gemm_sp<true>,  cudaFuncAttributeMaxDynamicSharedMemorySize, GEMM_SMEM);
    cudaFuncSetAttribute(flash_kernel,   cudaFuncAttributeMaxDynamicSharedMemorySize, FLASH_SMEM);

    // 0) pre-process inputs
    split_f16_kernel<<<(LQ * DIM / 4 + 255) / 256, 256>>>(x, xh, xl, LQ * DIM / 4);
    round_f16_kernel<<<(QKV_N * DIM / 4 + 255) / 256, 256>>>(qkv_w, wh, QKV_N * DIM / 4);
    round_f16_kernel<<<(DIM * DIM / 4 + 255) / 256, 256>>>(proj_w, pwh, DIM * DIM / 4);

    // 1) qkv = x @ qkv_w^T  (exact-x @ fp16(w), 2 MMAs)
    {
        dim3 grid(QKV_N / 128, LQ / 128);
        gemm_sp<false><<<grid, 256, GEMM_SMEM>>>(xh, xl, wh, qkv, nullptr,
                                                 LQ, QKV_N, DIM, DIM, DIM, QKV_N);
    }

    // 2) RMSNorm + RoPE -> q,k fp16; v -> fp16 transposed
    norm_rope_split<<<3 * NH * LQ, 128>>>(pe, q_scale, k_scale);

    // 3) flash attention -> g_ah/g_al
    {
        dim3 grid(LQ / 128, NH);
        flash_kernel<<<grid, 256, FLASH_SMEM>>>();
    }

    // 4) out = att @ proj_w^T + proj_b  (exact-att @ fp16(w), 2 MMAs)
    {
        dim3 grid(DIM / 128, LQ / 128);
        gemm_sp<true><<<grid, 256, GEMM_SMEM>>>(ah, al, pwh, out, proj_b,
                                                LQ, DIM, DIM, DIM, DIM, DIM);
    }
}

// round 17
// speedup vs baseline: 4.1695x; 1.0297x over previous
#include <cuda_runtime.h>
#include <cuda_bf16.h>
#include <cuda_fp16.h>
#include <cstdint>

// ---------------------------------------------------------------------------
#define LQ    2048
#define DIM   2048
#define NH    16
#define HD    128
#define QKV_N 6144
#define SCALE 0.08838834764831845f   // 1/sqrt(128)

// ---------------------------------------------------------------------------
// Scratch (__device__ globals; allocation-free rule)
// ---------------------------------------------------------------------------
__device__ float  g_qkv[(size_t)LQ * QKV_N];                  // fp32 qkv
__device__ __half g_xh[(size_t)LQ * DIM],  g_xl[(size_t)LQ * DIM];   // x split fp16
__device__ __half g_wh[(size_t)QKV_N * DIM];                  // qkv_w rounded fp16
__device__ __half g_pwh[(size_t)DIM * DIM];                   // proj_w rounded fp16
__device__ __half g_qs[(size_t)LQ * DIM],  g_ks[(size_t)LQ * DIM];   // q,k fp16
__device__ __half g_vt[(size_t)DIM * LQ];                     // V^T fp16
__device__ __half g_ah[(size_t)LQ * DIM],  g_al[(size_t)LQ * DIM];   // attn out split fp16

// ---------------------------------------------------------------------------
// helpers
// ---------------------------------------------------------------------------
__device__ __forceinline__ void split2_f16(float x, float y, uint32_t& hw, uint32_t& lw) {
    __half hx = __float2half_rn(x);
    __half hy = __float2half_rn(y);
    __half lx = __float2half_rn(x - __half2float(hx));
    __half ly = __float2half_rn(y - __half2float(hy));
    __half2 hp, lp;
    hp.x = hx; hp.y = hy;
    lp.x = lx; lp.y = ly;
    hw = *(uint32_t*)&hp;
    lw = *(uint32_t*)&lp;
}
__device__ __forceinline__ uint32_t round2_f16(float x, float y) {
    __half2 p = __floats2half2_rn(x, y);
    return *(uint32_t*)&p;
}
__device__ __forceinline__ uint32_t saddr(const void* p) {
    return (uint32_t)__cvta_generic_to_shared(p);
}
__device__ __forceinline__ void cp16(uint32_t dst, const void* src) {
    asm volatile("cp.async.cg.shared.global [%0], [%1], 16;" :: "r"(dst), "l"(src));
}
#define CP_COMMIT() asm volatile("cp.async.commit_group;")
#define CP_WAIT0()  asm volatile("cp.async.wait_group 0;")
#define CP_WAIT1()  asm volatile("cp.async.wait_group 1;")

__device__ __forceinline__ void ldsm4(uint32_t& r0, uint32_t& r1, uint32_t& r2, uint32_t& r3,
                                      uint32_t addr) {
    asm volatile("ldmatrix.sync.aligned.m8n8.x4.shared.b16 {%0,%1,%2,%3}, [%4];"
                 : "=r"(r0), "=r"(r1), "=r"(r2), "=r"(r3) : "r"(addr));
}
__device__ __forceinline__ void mma_f16(float c[4],
                                        uint32_t a0, uint32_t a1, uint32_t a2, uint32_t a3,
                                        uint32_t b0, uint32_t b1) {
    asm("mma.sync.aligned.m16n8k16.row.col.f32.f16.f16.f32 "
        "{%0,%1,%2,%3}, {%4,%5,%6,%7}, {%8,%9}, {%0,%1,%2,%3};"
        : "+f"(c[0]), "+f"(c[1]), "+f"(c[2]), "+f"(c[3])
        : "r"(a0), "r"(a1), "r"(a2), "r"(a3), "r"(b0), "r"(b1));
}

// ---------------------------------------------------------------------------
// fused pre-processing: split x -> (xh, xl); round qkv_w, proj_w -> fp16.
// One grid-partitioned launch; per-element math identical to R15 kernels.
// ---------------------------------------------------------------------------
__global__ void prep_kernel(const float* __restrict__ x,
                            const float* __restrict__ w,
                            const float* __restrict__ pw)
{
    const long NX = (long)LQ * DIM / 4;        // x float4 count
    const long NW = (long)QKV_N * DIM / 4;     // qkv_w float4 count
    const long NP = (long)DIM * DIM / 4;       // proj_w float4 count
    const long i = (long)blockIdx.x * blockDim.x + threadIdx.x;

    if (i < NX) {
        const float4 v = ((const float4*)x)[i];
        uint32_t h01, l01, h23, l23;
        split2_f16(v.x, v.y, h01, l01);
        split2_f16(v.z, v.w, h23, l23);
        uint2 th = {h01, h23}, tl = {l01, l23};
        ((uint2*)g_xh)[i] = th;
        ((uint2*)g_xl)[i] = tl;
    } else if (i < NX + NW) {
        const long j = i - NX;
        const float4 v = ((const float4*)w)[j];
        uint2 t = {round2_f16(v.x, v.y), round2_f16(v.z, v.w)};
        ((uint2*)g_wh)[j] = t;
    } else if (i < NX + NW + NP) {
        const long j = i - NX - NW;
        const float4 v = ((const float4*)pw)[j];
        uint2 t = {round2_f16(v.x, v.y), round2_f16(v.z, v.w)};
        ((uint2*)g_pwh)[j] = t;
    }
}

// ---------------------------------------------------------------------------
// fp16x2 A-split GEMM (A@B^T): C = (Ah+Al) @ Bh  (+bias)   [unchanged R15]
// ---------------------------------------------------------------------------
template<bool BIAS>
__global__ __launch_bounds__(256, 2)
void gemm_sp(const __half* __restrict__ ah, const __half* __restrict__ al,
             const __half* __restrict__ bh,
             float* __restrict__ C, const float* __restrict__ bias,
             int M, int N, int K, int lda, int ldb, int ldc)
{
    extern __shared__ uint32_t sm[];
    const uint32_t smb = saddr(sm);
    const int tid  = threadIdx.x;
    const int warp = tid >> 5, lane = tid & 31;
    const int wm = (warp >> 2) * 64, wn = (warp & 3) * 32;
    const int m0 = blockIdx.y * 128, n0 = blockIdx.x * 128;

    const int arow = (lane & 7) + ((lane >> 3) & 1) * 8;
    const int akp  = (lane >> 4) * 4;
    const int brow = (lane & 7) + (lane >> 4) * 8;
    const int bkp  = ((lane >> 3) & 1) * 4;

    float acc[4][4][4];
#pragma unroll
    for (int i = 0; i < 4; i++)
#pragma unroll
        for (int j = 0; j < 4; j++)
#pragma unroll
            for (int r = 0; r < 4; r++) acc[i][j][r] = 0.f;

    auto stage = [&](int s, int k0) {
        uint32_t* B0 = sm + s * 7680;
#pragma unroll
        for (int i = tid; i < 512; i += 256) {
            const int r = i >> 2, c = i & 3;
            cp16(saddr(B0        + r * 20 + c * 4), (const uint4*)(ah + (size_t)(m0 + r) * lda + k0) + c);
            cp16(saddr(B0 + 2560 + r * 20 + c * 4), (const uint4*)(al + (size_t)(m0 + r) * lda + k0) + c);
            cp16(saddr(B0 + 5120 + r * 20 + c * 4), (const uint4*)(bh + (size_t)(n0 + r) * ldb + k0) + c);
        }
    };

    const int T = K / 32;
    stage(0, 0);
    CP_COMMIT();

    for (int t = 0; t < T; t++) {
        if (t + 1 < T) {
            stage((t + 1) & 1, (t + 1) * 32);
            CP_COMMIT();
            CP_WAIT1();
        } else {
            CP_WAIT0();
        }
        __syncthreads();

        const uint32_t stg = smb + (t & 1) * 30720;

#pragma unroll
        for (int kc = 0; kc < 16; kc += 8) {
            uint32_t bf[4][2];
#pragma unroll
            for (int g = 0; g < 2; g++) {
                const uint32_t bi = (uint32_t)((wn + g * 16 + brow) * 20 + kc + bkp) * 4;
                ldsm4(bf[2*g][0], bf[2*g][1], bf[2*g+1][0], bf[2*g+1][1], stg + 20480 + bi);
            }
#pragma unroll
            for (int mt = 0; mt < 4; mt++) {
                const uint32_t ai = (uint32_t)((wm + mt * 16 + arow) * 20 + kc + akp) * 4;
                uint32_t ah0, ah1, ah2, ah3, al0, al1, al2, al3;
                ldsm4(ah0, ah1, ah2, ah3, stg + ai);
                ldsm4(al0, al1, al2, al3, stg + 10240 + ai);
#pragma unroll
                for (int nt = 0; nt < 4; nt++)
                    mma_f16(acc[mt][nt], al0, al1, al2, al3, bf[nt][0], bf[nt][1]);
#pragma unroll
                for (int nt = 0; nt < 4; nt++)
                    mma_f16(acc[mt][nt], ah0, ah1, ah2, ah3, bf[nt][0], bf[nt][1]);
            }
        }
        __syncthreads();
    }

    const int cr = lane >> 2, cc = (lane & 3) * 2;
#pragma unroll
    for (int mt = 0; mt < 4; mt++) {
#pragma unroll
        for (int nt = 0; nt < 4; nt++) {
            const int m = m0 + wm + mt * 16 + cr;
            const int n = n0 + wn + nt * 8 + cc;
            float2 v0, v1;
            v0.x = acc[mt][nt][0]; v0.y = acc[mt][nt][1];
            v1.x = acc[mt][nt][2]; v1.y = acc[mt][nt][3];
            if (BIAS) {
                const float b0 = bias[n], b1 = bias[n + 1];
                v0.x += b0; v0.y += b1;
                v1.x += b0; v1.y += b1;
            }
            *(float2*)(C + (size_t)m       * ldc + n) = v0;
            *(float2*)(C + (size_t)(m + 8) * ldc + n) = v1;
        }
    }
}

// ---------------------------------------------------------------------------
// norm_rope_split: RMSNorm+RoPE on q/k -> fp16; v -> fp16 transposed. [unchanged]
// ---------------------------------------------------------------------------
__global__ void norm_rope_split(const float* __restrict__ pe,
                                const float* __restrict__ q_scale,
                                const float* __restrict__ k_scale)
{
    const int idx = blockIdx.x;
    const int l   = idx & (LQ - 1);
    const int h   = (idx >> 11) & (NH - 1);
    const int qk  = idx >> 15;                  // 0=q, 1=k, 2=v
    const int d   = threadIdx.x;
    const int lane = d & 31, warp = d >> 5;

    const float* row = g_qkv + (size_t)l * QKV_N + qk * DIM + h * HD;
    const float t = row[d];

    if (qk == 2) {
        g_vt[(size_t)(h * HD + d) * LQ + l] = __float2half_rn(t);
        return;
    }

    float ss = t * t;
#pragma unroll
    for (int o = 16; o > 0; o >>= 1) ss += __shfl_xor_sync(0xFFFFFFFFu, ss, o);
    __shared__ float red[4];
    if (lane == 0) red[warp] = ss;
    __syncthreads();
    const float tot = red[0] + red[1] + red[2] + red[3];
    const float rrms = rsqrtf(tot * (1.0f / HD) + 1e-6f);

    const float* scale = qk ? k_scale : q_scale;
    const float tn = t * rrms * scale[d];

    const float other = __shfl_xor_sync(0xFFFFFFFFu, tn, 1);
    const int j = d >> 1, s = d & 1;
    const float* pp = pe + ((size_t)l * (HD / 2) + j) * 4 + s * 2;
    const float te = (s == 0) ? tn : other;
    const float to = (s == 0) ? other : tn;
    const float roped = pp[0] * te + pp[1] * to;

    __shared__ float buf[HD];
    buf[d] = roped;
    __syncthreads();
    if (d < 64) {
        const uint32_t w = round2_f16(buf[2 * d], buf[2 * d + 1]);
        const size_t o32 = ((size_t)l * DIM + h * HD) / 2 + d;
        if (qk == 0) ((uint32_t*)g_qs)[o32] = w;
        else         ((uint32_t*)g_ks)[o32] = w;
    }
}

// ---------------------------------------------------------------------------
// Flash attention: fp16 scores + PV, DOUBLE-BUFFERED K/V staging.
// smem (u32): Qs[8704] | Ks0[8704] | Ks1[8704] | Vs0[8704] | Vs1[8704]
//             | redm[512] | redl[512]  = 44544 u32 = 178176 B.
// Staging of block kb+1 overlaps compute of block kb. P aliases Ks[cur].
// ---------------------------------------------------------------------------
__global__ __launch_bounds__(256, 1)
void flash_kernel()
{
    extern __shared__ uint32_t sm[];
    const uint32_t smb = saddr(sm);
    float* redm = (float*)(sm + 43520);
    float* redl = (float*)(sm + 44032);

    const int tid  = threadIdx.x;
    const int warp = tid >> 5, lane = tid & 31;
    const int wm = (warp >> 2) * 64, wn = (warp & 3) * 32;
    const int wr = warp >> 2, wc = warp & 3;
    const int qb = blockIdx.x, h = blockIdx.y;
    const int ar = lane >> 2;
    const int l3 = lane & 3;

    const int arow = (lane & 7) + ((lane >> 3) & 1) * 8;
    const int akp  = (lane >> 4) * 4;
    const int brow = (lane & 7) + (lane >> 4) * 8;
    const int bkp  = ((lane >> 3) & 1) * 4;

    // stage Q block (group 0)
#pragma unroll
    for (int i = tid; i < 2048; i += 256) {
        const int r = i >> 4, c = i & 15;
        const size_t off = ((size_t)(qb * 128 + r) * DIM + h * HD) / 2;
        cp16(saddr(sm + r * 68 + c * 4), (const uint4*)((const uint32_t*)g_qs + off) + c);
    }
    CP_COMMIT();

    // stage K/V for block kb into buffer b
    auto stageKV = [&](int kb, int b) {
        uint32_t* Kd = sm + 8704  + b * 8704;
        uint32_t* Vd = sm + 26112 + b * 8704;
#pragma unroll
        for (int i = tid; i < 2048; i += 256) {
            const int r = i >> 4, c = i & 15;
            const size_t off = ((size_t)(kb * 128 + r) * DIM + h * HD) / 2;
            cp16(saddr(Kd + r * 68 + c * 4), (const uint4*)((const uint32_t*)g_ks + off) + c);
        }
#pragma unroll
        for (int i = tid; i < 2048; i += 256) {
            const int r = i >> 4, c = i & 15;
            const size_t off = ((size_t)(h * HD + r) * LQ + kb * 128) / 2;
            cp16(saddr(Vd + r * 68 + c * 4), (const uint4*)((const uint32_t*)g_vt + off) + c);
        }
    };

    stageKV(0, 0);
    CP_COMMIT();      // group 1

    float o[4][4][4];
    float s[4][4][4];
    float mst[4][2], lst[4][2], corr[4][2];
#pragma unroll
    for (int i = 0; i < 4; i++) {
#pragma unroll
        for (int j = 0; j < 4; j++)
#pragma unroll
            for (int r = 0; r < 4; r++) o[i][j][r] = 0.f;
        mst[i][0] = -1e30f; mst[i][1] = -1e30f;
        lst[i][0] = 0.f;    lst[i][1] = 0.f;
    }

    for (int kb = 0; kb < 16; kb++) {
        if (kb) __syncthreads();   // all warps done with PV of kb-1 (buffer being restaged)

        if (kb + 1 < 16) {
            stageKV(kb + 1, (kb + 1) & 1);
            CP_COMMIT();
            CP_WAIT1();            // current block's staging complete; next in flight
        } else {
            CP_WAIT0();
        }
        __syncthreads();

        const int cur = kb & 1;
        const uint32_t kbase = 34816  + (uint32_t)cur * 34816;   // Ks[cur] byte offset
        const uint32_t vbase = 104448 + (uint32_t)cur * 34816;   // Vs[cur] byte offset
        uint32_t* Ps = sm + 8704 + cur * 8704;                   // P aliases Ks[cur]

        // ---- S = Q @ K^T (fp16 single-MMA) ----
#pragma unroll
        for (int i = 0; i < 4; i++)
#pragma unroll
            for (int j = 0; j < 4; j++)
#pragma unroll
                for (int r = 0; r < 4; r++) s[i][j][r] = 0.f;

#pragma unroll
        for (int kc = 0; kc < 64; kc += 8) {
            uint32_t bf[4][2];
#pragma unroll
            for (int g = 0; g < 2; g++) {
                const uint32_t bi = (uint32_t)((wn + g * 16 + brow) * 68 + kc + bkp) * 4;
                ldsm4(bf[2*g][0], bf[2*g][1], bf[2*g+1][0], bf[2*g+1][1], smb + kbase + bi);
            }
#pragma unroll
            for (int mt = 0; mt < 4; mt++) {
                const uint32_t ai = (uint32_t)((wm + mt * 16 + arow) * 68 + kc + akp) * 4;
                uint32_t q0, q1, q2, q3;
                ldsm4(q0, q1, q2, q3, smb + ai);
#pragma unroll
                for (int nt = 0; nt < 4; nt++)
                    mma_f16(s[mt][nt], q0, q1, q2, q3, bf[nt][0], bf[nt][1]);
            }
        }

        // ---- row max ----
#pragma unroll
        for (int mt = 0; mt < 4; mt++) {
#pragma unroll
            for (int hf = 0; hf < 2; hf++) {
                float mx = -1e30f;
#pragma unroll
                for (int nt = 0; nt < 4; nt++) {
                    mx = fmaxf(mx, s[mt][nt][2 * hf]);
                    mx = fmaxf(mx, s[mt][nt][2 * hf + 1]);
                }
                mx = fmaxf(mx, __shfl_xor_sync(0xFFFFFFFFu, mx, 1));
                mx = fmaxf(mx, __shfl_xor_sync(0xFFFFFFFFu, mx, 2));
                if (l3 == 0) redm[wr * 256 + wc * 64 + mt * 16 + ar + 8 * hf] = mx;
            }
        }
        __syncthreads();   // all S-loop LDSM of Ks[cur] complete before P writes

        float psum[4][2];
#pragma unroll
        for (int mt = 0; mt < 4; mt++) {
#pragma unroll
            for (int hf = 0; hf < 2; hf++) {
                const int r = mt * 16 + ar + 8 * hf;
                float gm = redm[wr * 256 + r];
                gm = fmaxf(gm, redm[wr * 256 + 64 + r]);
                gm = fmaxf(gm, redm[wr * 256 + 128 + r]);
                gm = fmaxf(gm, redm[wr * 256 + 192 + r]);
                const float mnew = fmaxf(mst[mt][hf], gm);
                corr[mt][hf] = __expf((mst[mt][hf] - mnew) * SCALE);
                mst[mt][hf] = mnew;
                psum[mt][hf] = 0.f;
            }
        }

        // rescale O, exponentiate S -> P (fp16 into Ps), partial sums
#pragma unroll
        for (int mt = 0; mt < 4; mt++) {
#pragma unroll
            for (int nt = 0; nt < 4; nt++) {
#pragma unroll
                for (int hf = 0; hf < 2; hf++) {
                    o[mt][nt][2 * hf]     *= corr[mt][hf];
                    o[mt][nt][2 * hf + 1] *= corr[mt][hf];
                    const float p0 = __expf((s[mt][nt][2 * hf]     - mst[mt][hf]) * SCALE);
                    const float p1 = __expf((s[mt][nt][2 * hf + 1] - mst[mt][hf]) * SCALE);
                    psum[mt][hf] += p0 + p1;
                    const __half2 hp = __floats2half2_rn(p0, p1);
                    const int q  = wm + mt * 16 + ar + 8 * hf;
                    const int kp = (wn >> 1) + nt * 4 + l3;
                    Ps[q * 68 + kp] = *(const uint32_t*)&hp;
                }
            }
        }
#pragma unroll
        for (int mt = 0; mt < 4; mt++) {
#pragma unroll
            for (int hf = 0; hf < 2; hf++) {
                float sv = psum[mt][hf];
                sv += __shfl_xor_sync(0xFFFFFFFFu, sv, 1);
                sv += __shfl_xor_sync(0xFFFFFFFFu, sv, 2);
                if (l3 == 0) redl[wr * 256 + wc * 64 + mt * 16 + ar + 8 * hf] = sv;
            }
        }
        __syncthreads();   // redl ready + P writes visible

#pragma unroll
        for (int mt = 0; mt < 4; mt++) {
#pragma unroll
            for (int hf = 0; hf < 2; hf++) {
                const int r = mt * 16 + ar + 8 * hf;
                const float gs = redl[wr * 256 + r] + redl[wr * 256 + 64 + r]
                               + redl[wr * 256 + 128 + r] + redl[wr * 256 + 192 + r];
                lst[mt][hf] = lst[mt][hf] * corr[mt][hf] + gs;
            }
        }

        // ---- O += P @ V (fp16) ----
#pragma unroll
        for (int kc = 0; kc < 64; kc += 8) {
            uint32_t bf[4][2];
#pragma unroll
            for (int g = 0; g < 2; g++) {
                const uint32_t bi = (uint32_t)((wn + g * 16 + brow) * 68 + kc + bkp) * 4;
                ldsm4(bf[2*g][0], bf[2*g][1], bf[2*g+1][0], bf[2*g+1][1], smb + vbase + bi);
            }
#pragma unroll
            for (int mt = 0; mt < 4; mt++) {
                const uint32_t ai = (uint32_t)((wm + mt * 16 + arow) * 68 + kc + akp) * 4;
                uint32_t p0, p1, p2, p3;
                ldsm4(p0, p1, p2, p3, smb + kbase + ai);
#pragma unroll
                for (int nt = 0; nt < 4; nt++)
                    mma_f16(o[mt][nt], p0, p1, p2, p3, bf[nt][0], bf[nt][1]);
            }
        }
    }

    // ---- epilogue: O/l -> fp16 split -> g_ah/g_al ----
#pragma unroll
    for (int mt = 0; mt < 4; mt++) {
#pragma unroll
        for (int hf = 0; hf < 2; hf++) {
            const float inv = 1.0f / lst[mt][hf];
            const int q = qb * 128 + wm + mt * 16 + ar + 8 * hf;
#pragma unroll
            for (int nt = 0; nt < 4; nt++) {
                const float o0 = o[mt][nt][2 * hf] * inv;
                const float o1 = o[mt][nt][2 * hf + 1] * inv;
                uint32_t hw, lw;
                split2_f16(o0, o1, hw, lw);
                const size_t idx = ((size_t)q * DIM + h * HD + wn + nt * 8) / 2 + l3;
                ((uint32_t*)g_ah)[idx] = hw;
                ((uint32_t*)g_al)[idx] = lw;
            }
        }
    }
}

// ---------------------------------------------------------------------------
// Launch
// ---------------------------------------------------------------------------
extern "C" void kernel_launch(void* const* d_in, const int* in_sizes, int n_in,
                              void* d_out, int out_size)
{
    const float* x       = (const float*)d_in[0];
    const float* pe      = (const float*)d_in[1];
    const float* qkv_w   = (const float*)d_in[2];
    const float* q_scale = (const float*)d_in[3];
    const float* k_scale = (const float*)d_in[4];
    const float* proj_w  = (const float*)d_in[5];
    const float* proj_b  = (const float*)d_in[6];
    float* out = (float*)d_out;

    float* qkv;
    __half *xh, *xl, *wh, *pwh, *ah, *al;
    cudaGetSymbolAddress((void**)&qkv, g_qkv);
    cudaGetSymbolAddress((void**)&xh,  g_xh);
    cudaGetSymbolAddress((void**)&xl,  g_xl);
    cudaGetSymbolAddress((void**)&wh,  g_wh);
    cudaGetSymbolAddress((void**)&pwh, g_pwh);
    cudaGetSymbolAddress((void**)&ah,  g_ah);
    cudaGetSymbolAddress((void**)&al,  g_al);

    const int GEMM_SMEM  = 61440;    // 2 x 30720
    const int FLASH_SMEM = 178176;   // 44544 u32
    cudaFuncSetAttribute(gemm_sp<false>, cudaFuncAttributeMaxDynamicSharedMemorySize, GEMM_SMEM);
    cudaFuncSetAttribute(gemm_sp<true>,  cudaFuncAttributeMaxDynamicSharedMemorySize, GEMM_SMEM);
    cudaFuncSetAttribute(flash_kernel,   cudaFuncAttributeMaxDynamicSharedMemorySize, FLASH_SMEM);

    // 0) fused pre-processing (x split, weights rounded)
    {
        const long total = (long)LQ * DIM / 4 + (long)QKV_N * DIM / 4 + (long)DIM * DIM / 4;
        prep_kernel<<<(int)((total + 255) / 256), 256>>>(x, qkv_w, proj_w);
    }

    // 1) qkv = x @ qkv_w^T  (exact-x @ fp16(w), 2 MMAs)
    {
        dim3 grid(QKV_N / 128, LQ / 128);
        gemm_sp<false><<<grid, 256, GEMM_SMEM>>>(xh, xl, wh, qkv, nullptr,
                                                 LQ, QKV_N, DIM, DIM, DIM, QKV_N);
    }

    // 2) RMSNorm + RoPE -> q,k fp16; v -> fp16 transposed
    norm_rope_split<<<3 * NH * LQ, 128>>>(pe, q_scale, k_scale);

    // 3) flash attention (double-buffered K/V) -> g_ah/g_al
    {
        dim3 grid(LQ / 128, NH);
        flash_kernel<<<grid, 256, FLASH_SMEM>>>();
    }

    // 4) out = att @ proj_w^T + proj_b  (exact-att @ fp16(w), 2 MMAs)
    {
        dim3 grid(DIM / 128, LQ / 128);
        gemm_sp<true><<<grid, 256, GEMM_SMEM>>>(ah, al, pwh, out, proj_b,
                                                LQ, DIM, DIM, DIM, DIM, DIM);
    }
}